// round 13
// baseline (speedup 1.0000x reference)
#include <cuda_runtime.h>
#include <cuda_bf16.h>
#include <cuda_fp16.h>
#include <math.h>
#include <stdint.h>

// ---------------- problem constants ----------------
#define BB      4
#define LL      4096
#define DMODEL  512
#define DINNER  1024
#define DSTATE  64
#define HEADD   64
#define NHEADS  16
#define CONVD   1152
#define NPROJ   2192
#define NPROJ_PAD 2304      // 18*128
#define BL      (BB*LL)

// scan segmentation
#define SSEG    32
#define SEGL    (LL / SSEG)   // 128

// ---------------- scratch ----------------
__device__ float g_zx [(size_t)BL * NPROJ];
__device__ float g_xc [(size_t)BL * CONVD];
__device__ float g_ys [(size_t)BL * DINNER];
__device__ float g_y2 [(size_t)BL * DMODEL];
__device__ float g_dt [(size_t)BL * NHEADS];   // exact fp32 dt_raw
__device__ float g_hseg[64 * SSEG * 4096];
__device__ float g_hst [64 * SSEG * 4096];
__device__ float g_cum [64 * LL];

// pre-split fp16 operands (all GEMMs now fp16 2-pass)
__device__ __half g_xhi [(size_t)BL * DMODEL],  g_xlo [(size_t)BL * DMODEL];
__device__ __half g_winh[(size_t)NPROJ_PAD * DMODEL], g_winl[(size_t)NPROJ_PAD * DMODEL];
__device__ __half g_woh [DMODEL * DINNER], g_wol [DMODEL * DINNER];
__device__ __half g_w1h [DINNER * DMODEL], g_w1l [DINNER * DMODEL];
__device__ __half g_w2h [DMODEL * DINNER], g_w2l [DMODEL * DINNER];
__device__ __half g_ybh [(size_t)BL * DINNER], g_ybl [(size_t)BL * DINNER];
__device__ __half g_ylnh[(size_t)BL * DMODEL], g_ylnl[(size_t)BL * DMODEL];
__device__ __half g_h1h [(size_t)BL * DINNER], g_h1l [(size_t)BL * DINNER];

// ================= helpers =================
__device__ __forceinline__ unsigned pack16(unsigned short a, unsigned short b) {
    return (unsigned)a | ((unsigned)b << 16);
}
__device__ __forceinline__ void ldsm_x4(unsigned &r0, unsigned &r1,
                                        unsigned &r2, unsigned &r3, unsigned addr) {
    asm volatile("ldmatrix.sync.aligned.m8n8.x4.shared.b16 {%0,%1,%2,%3}, [%4];"
                 : "=r"(r0), "=r"(r1), "=r"(r2), "=r"(r3) : "r"(addr));
}
__device__ __forceinline__ void mma_hf(float* c, const unsigned* a, const unsigned* b) {
    asm volatile(
        "mma.sync.aligned.m16n8k16.row.col.f32.f16.f16.f32 "
        "{%0,%1,%2,%3}, {%4,%5,%6,%7}, {%8,%9}, {%0,%1,%2,%3};"
        : "+f"(c[0]), "+f"(c[1]), "+f"(c[2]), "+f"(c[3])
        : "r"(a[0]), "r"(a[1]), "r"(a[2]), "r"(a[3]), "r"(b[0]), "r"(b[1]));
}
__device__ __forceinline__ void cp16(unsigned dst, const void* src) {
    asm volatile("cp.async.cg.shared.global [%0], [%1], 16;" :: "r"(dst), "l"(src));
}

#define TILE_BYTES   16384
#define BUF_BYTES    (2 * TILE_BYTES)
#define GSM_BYTES    (2 * BUF_BYTES)   // 64KB, 2-stage

// ================= GEMM: C = A @ W^T, fp16 2-pass (AhBh + AlBh) ==================
// EPI: 0 none, 1 +bias, 2 +bias+silu.  OSPLIT: 1 -> fp16 hi/lo out.
template<int EPI, int OSPLIT>
__global__ void __launch_bounds__(256, 2)
hgemm2_kernel(const __half* __restrict__ Ahi_, const __half* __restrict__ Alo_,
              const __half* __restrict__ Whi_,
              const float* __restrict__ bias, float* __restrict__ C,
              __half* __restrict__ Chi, __half* __restrict__ Clo,
              int M, int N, int K)
{
    const unsigned short* Ahi = (const unsigned short*)Ahi_;
    const unsigned short* Alo = (const unsigned short*)Alo_;
    const unsigned short* Whi = (const unsigned short*)Whi_;

    extern __shared__ char smem[];

    const int tid  = threadIdx.x;
    const int lane = tid & 31;
    const int wid  = tid >> 5;
    const int wm   = wid & 1;
    const int wn   = wid >> 1;
    const int m0   = blockIdx.y * 128;
    const int n0   = blockIdx.x * 128;

    const int lrow = tid >> 1;
    const int half = tid & 1;
    const int rsw  = lrow & 7;
    const int c0 = 2 * half, c1 = 2 * half + 1, c2 = 4 + 2 * half, c3 = 5 + 2 * half;

    const unsigned s_u32 = (unsigned)__cvta_generic_to_shared(&smem[0]);
    const unsigned abase = s_u32 + (unsigned)(lrow * 128);
    const unsigned bbase = s_u32 + (unsigned)(TILE_BYTES + lrow * 128);

    unsigned aBase[4]; int aSw[4];
    const int kcA = lane >> 4;
#pragma unroll
    for (int mi = 0; mi < 4; mi++) {
        int r = wm * 64 + mi * 16 + (lane & 7) + ((lane >> 3) & 1) * 8;
        aBase[mi] = s_u32 + (unsigned)(r * 128);
        aSw[mi] = r & 7;
    }
    unsigned bBase[2]; int bSw[2];
    const int kcB = (lane >> 3) & 1;
#pragma unroll
    for (int pj = 0; pj < 2; pj++) {
        int r = wn * 32 + pj * 16 + ((lane >> 4) & 1) * 8 + (lane & 7);
        bBase[pj] = s_u32 + (unsigned)(TILE_BYTES + r * 128);
        bSw[pj] = r & 7;
    }

    float acc[4][4][4];
#pragma unroll
    for (int i = 0; i < 4; i++)
#pragma unroll
        for (int j = 0; j < 4; j++)
#pragma unroll
            for (int q = 0; q < 4; q++) acc[i][j][q] = 0.f;

    auto issue = [&](int k0, int buf) {
        unsigned bo = (unsigned)(buf * BUF_BYTES);
        const unsigned short* sa  = Ahi + (size_t)(m0 + lrow) * K + k0 + half * 16;
        const unsigned short* sal = Alo + (size_t)(m0 + lrow) * K + k0 + half * 16;
        const unsigned short* sb  = Whi + (size_t)(n0 + lrow) * K + k0 + half * 16;
        cp16(abase + bo + (unsigned)((c0 ^ rsw) * 16), sa);
        cp16(abase + bo + (unsigned)((c1 ^ rsw) * 16), sa + 8);
        cp16(abase + bo + (unsigned)((c2 ^ rsw) * 16), sal);
        cp16(abase + bo + (unsigned)((c3 ^ rsw) * 16), sal + 8);
        cp16(bbase + bo + (unsigned)((c0 ^ rsw) * 16), sb);
        cp16(bbase + bo + (unsigned)((c1 ^ rsw) * 16), sb + 8);
        asm volatile("cp.async.commit_group;" ::: "memory");
    };

    auto do_ks = [&](int ks, unsigned boff) {
        unsigned bh[4][2];
#pragma unroll
        for (int pj = 0; pj < 2; pj++) {
            unsigned r0, r1, r2, r3;
            ldsm_x4(r0, r1, r2, r3,
                    bBase[pj] + boff + (unsigned)((((ks * 2 + kcB)) ^ bSw[pj]) * 16));
            bh[pj * 2][0] = r0; bh[pj * 2][1] = r1;
            bh[pj * 2 + 1][0] = r2; bh[pj * 2 + 1][1] = r3;
        }
#pragma unroll
        for (int mi = 0; mi < 4; mi++) {
            unsigned a[4];
            ldsm_x4(a[0], a[1], a[2], a[3],
                    aBase[mi] + boff + (unsigned)((((ks * 2 + kcA)) ^ aSw[mi]) * 16));
#pragma unroll
            for (int nj = 0; nj < 4; nj++) mma_hf(acc[mi][nj], a, bh[nj]);
            ldsm_x4(a[0], a[1], a[2], a[3],
                    aBase[mi] + boff + (unsigned)((((ks * 2 + kcA + 4)) ^ aSw[mi]) * 16));
#pragma unroll
            for (int nj = 0; nj < 4; nj++) mma_hf(acc[mi][nj], a, bh[nj]);
        }
    };

    issue(0, 0);
    const int nk = K >> 5;
    for (int it = 0; it < nk; it++) {
        asm volatile("cp.async.wait_group 0;" ::: "memory");
        __syncthreads();
        if (it + 1 < nk) issue((it + 1) * 32, (it + 1) & 1);
        const unsigned boff = (unsigned)((it & 1) * BUF_BYTES);
        do_ks(0, boff);
        do_ks(1, boff);
    }

    // epilogue
    const int row0 = m0 + wm * 64 + (lane >> 2);
    const int col0 = n0 + wn * 32 + (lane & 3) * 2;
#pragma unroll
    for (int mi = 0; mi < 4; mi++) {
#pragma unroll
        for (int nj = 0; nj < 4; nj++) {
            int col = col0 + nj * 8;
            if (col < N) {
                float b0 = 0.f, b1 = 0.f;
                if (EPI >= 1) { b0 = bias[col]; b1 = bias[col + 1]; }
                float v0 = acc[mi][nj][0] + b0;
                float v1 = acc[mi][nj][1] + b1;
                float v2 = acc[mi][nj][2] + b0;
                float v3 = acc[mi][nj][3] + b1;
                if (EPI == 2) {
                    v0 = v0 / (1.f + expf(-v0));
                    v1 = v1 / (1.f + expf(-v1));
                    v2 = v2 / (1.f + expf(-v2));
                    v3 = v3 / (1.f + expf(-v3));
                }
                int r = row0 + mi * 16;
                if (OSPLIT) {
                    __half h0 = __float2half(v0), h1 = __float2half(v1);
                    __half h2 = __float2half(v2), h3 = __float2half(v3);
                    __half l0 = __float2half(v0 - __half2float(h0));
                    __half l1 = __float2half(v1 - __half2float(h1));
                    __half l2 = __float2half(v2 - __half2float(h2));
                    __half l3 = __float2half(v3 - __half2float(h3));
                    *(unsigned*)&Chi[(size_t)r * N + col]       = pack16(*(unsigned short*)&h0, *(unsigned short*)&h1);
                    *(unsigned*)&Clo[(size_t)r * N + col]       = pack16(*(unsigned short*)&l0, *(unsigned short*)&l1);
                    *(unsigned*)&Chi[(size_t)(r + 8) * N + col] = pack16(*(unsigned short*)&h2, *(unsigned short*)&h3);
                    *(unsigned*)&Clo[(size_t)(r + 8) * N + col] = pack16(*(unsigned short*)&l2, *(unsigned short*)&l3);
                } else {
                    float2 p0; p0.x = v0; p0.y = v1;
                    float2 p1; p1.x = v2; p1.y = v3;
                    *(float2*)&C[(size_t)r * N + col] = p0;
                    *(float2*)&C[(size_t)(r + 8) * N + col] = p1;
                }
            }
        }
    }
}

// ---------------- exact dt: g_dt[bl,h] = dot(x[bl,:], in_proj_w[2176+h,:]) ------
__global__ void __launch_bounds__(128)
dt_exact_kernel(const float* __restrict__ x, const float* __restrict__ w,
                float* __restrict__ dtout)
{
    int row = blockIdx.x;
    __shared__ float sx[DMODEL];
    int tid = threadIdx.x;
#pragma unroll
    for (int i = 0; i < 4; i++) sx[tid + i * 128] = x[(size_t)row * DMODEL + tid + i * 128];
    __syncthreads();
    int h  = tid >> 3;        // 0..15
    int lt = tid & 7;         // 0..7
    const float* wr = w + (size_t)(2 * DINNER + 2 * DSTATE + h) * DMODEL + lt * 64;
    const float* xr = sx + lt * 64;
    float s0 = 0.f, s1 = 0.f;
#pragma unroll
    for (int k = 0; k < 64; k += 8) {
        float4 a0 = *(const float4*)(xr + k);
        float4 b0 = *(const float4*)(wr + k);
        float4 a1 = *(const float4*)(xr + k + 4);
        float4 b1 = *(const float4*)(wr + k + 4);
        s0 += a0.x * b0.x + a0.y * b0.y + a0.z * b0.z + a0.w * b0.w;
        s1 += a1.x * b1.x + a1.y * b1.y + a1.z * b1.z + a1.w * b1.w;
    }
    float s = s0 + s1;
    s += __shfl_xor_sync(0xffffffffu, s, 1);
    s += __shfl_xor_sync(0xffffffffu, s, 2);
    s += __shfl_xor_sync(0xffffffffu, s, 4);
    if (lt == 0) dtout[(size_t)row * NHEADS + h] = s;
}

// ---------------- splits ----------------
__global__ void __launch_bounds__(256)
split_hf_kernel(const float* __restrict__ src, __half* __restrict__ hi,
                __half* __restrict__ lo, int n, int total)
{
    int idx = blockIdx.x * blockDim.x + threadIdx.x;
    if (idx >= total) return;
    float v = (idx < n) ? src[idx] : 0.f;
    __half h = __float2half(v);
    hi[idx] = h;
    lo[idx] = __float2half(v - __half2float(h));
}
__global__ void __launch_bounds__(256)
w1eff_split_kernel(const float* __restrict__ w1, __half* __restrict__ hi,
                   __half* __restrict__ lo)
{
    int idx = blockIdx.x * blockDim.x + threadIdx.x;
    if (idx >= 1024 * 512) return;
    int n = idx / 512, k = idx % 512;
    float v = w1[n * 1024 + k] + w1[n * 1024 + 512 + k];
    __half h = __float2half(v);
    hi[idx] = h;
    lo[idx] = __float2half(v - __half2float(h));
}

// ---------------- conv (anti-causal) + silu, float4 vectorized ----------------
__global__ void __launch_bounds__(256)
conv_silu_kernel(const float* __restrict__ zx, const float* __restrict__ cw,
                 const float* __restrict__ cb, float* __restrict__ xc)
{
    size_t idx = (size_t)blockIdx.x * blockDim.x + threadIdx.x;
    if (idx >= (size_t)BL * (CONVD / 4)) return;
    int c4 = (int)(idx % (CONVD / 4));
    int bl = (int)(idx / (CONVD / 4));
    int l  = bl % LL;
    int c  = c4 * 4;

    float4 acc = *(const float4*)&cb[c];
    float4 w0 = *(const float4*)&cw[c * 4 + 0];
    float4 w1 = *(const float4*)&cw[c * 4 + 4];
    float4 w2 = *(const float4*)&cw[c * 4 + 8];
    float4 w3 = *(const float4*)&cw[c * 4 + 12];

    const float* base = zx + (size_t)bl * NPROJ + DINNER + c;
#pragma unroll
    for (int k = 0; k < 4; k++) {
        int off = 3 - k;
        if (l + off < LL) {
            float4 v = *(const float4*)(base + (size_t)off * NPROJ);
            acc.x += ((const float*)&w0)[k] * v.x;
            acc.y += ((const float*)&w1)[k] * v.y;
            acc.z += ((const float*)&w2)[k] * v.z;
            acc.w += ((const float*)&w3)[k] * v.w;
        }
    }
    acc.x = acc.x / (1.f + expf(-acc.x));
    acc.y = acc.y / (1.f + expf(-acc.y));
    acc.z = acc.z / (1.f + expf(-acc.z));
    acc.w = acc.w / (1.f + expf(-acc.w));
    *(float4*)&xc[(size_t)bl * CONVD + c] = acc;
}

// ---------------- scan pass 1 ----------------
__global__ void __launch_bounds__(256)
scan_seg1_kernel(const float* __restrict__ dtv, const float* __restrict__ xc,
                 const float* __restrict__ dt_bias, const float* __restrict__ A_log,
                 float* __restrict__ yout)
{
    int blk = blockIdx.x;
    int seg = blk & (SSEG - 1);
    int bh  = blk / SSEG;
    int b = bh >> 4, h = bh & 15;
    int tid = threadIdx.x;
    int pl = tid >> 2;
    int ng = tid & 3;

    float Acoef = -expf(A_log[h]);
    float dtb   = dt_bias[h];

    __shared__ float sB[2][8][64], sC[2][8][64], sX[2][8][64];
    __shared__ float sdt[2][8], sDA[2][8];

    float hs[16];
#pragma unroll
    for (int j = 0; j < 16; j++) hs[j] = 0.f;

    float rBC[4], rX[2], rDR = 0.f;
    const int sBeg = seg * SEGL;
    const int sEnd = sBeg + SEGL;

    float runP = 1.f;

    auto preload = [&](int s0) {
#pragma unroll
        for (int i = 0; i < 4; i++) {
            int e = tid + i * 256;
            int t = e >> 7, q = e & 127;
            int bl = b * LL + (LL - 1 - (s0 + t));
            rBC[i] = xc[(size_t)bl * CONVD + DINNER + q];
        }
#pragma unroll
        for (int i = 0; i < 2; i++) {
            int e = tid + i * 256;
            int t = e >> 6, j = e & 63;
            int bl = b * LL + (LL - 1 - (s0 + t));
            rX[i] = xc[(size_t)bl * CONVD + h * HEADD + j];
        }
        if (tid < 8) {
            int bl = b * LL + (LL - 1 - (s0 + tid));
            rDR = dtv[(size_t)bl * NHEADS + h];
        }
    };
    auto commit_smem = [&](int buf) {
#pragma unroll
        for (int i = 0; i < 4; i++) {
            int e = tid + i * 256;
            int t = e >> 7, q = e & 127;
            if (q < 64) sB[buf][t][q] = rBC[i]; else sC[buf][t][q - 64] = rBC[i];
        }
#pragma unroll
        for (int i = 0; i < 2; i++) {
            int e = tid + i * 256;
            int t = e >> 6, j = e & 63;
            sX[buf][t][j] = rX[i];
        }
        if (tid < 8) {
            float dr = rDR + dtb;
            float dt = (dr > 20.f) ? dr : log1pf(expf(dr));
            sdt[buf][tid] = dt;
            sDA[buf][tid] = expf(dt * Acoef);
        }
    };

    preload(sBeg);
    commit_smem(0);
    __syncthreads();

    for (int s0 = sBeg; s0 < sEnd; s0 += 8) {
        int buf = ((s0 - sBeg) >> 3) & 1;
        bool more = (s0 + 8) < sEnd;
        if (more) preload(s0 + 8);

        if (tid == 0) {
            float* cw = &g_cum[(size_t)bh * LL + s0];
#pragma unroll
            for (int t = 0; t < 8; t++) { runP *= sDA[buf][t]; cw[t] = runP; }
        }

        float yv[8];
#pragma unroll
        for (int t = 0; t < 8; t++) {
            float dA  = sDA[buf][t];
            float dtx = sdt[buf][t] * sX[buf][t][pl];
            float yp = 0.f;
#pragma unroll
            for (int u = 0; u < 4; u++) {
                float4 bb = *(const float4*)&sB[buf][t][u * 16 + ng * 4];
                hs[u*4+0] = hs[u*4+0] * dA + dtx * bb.x;
                hs[u*4+1] = hs[u*4+1] * dA + dtx * bb.y;
                hs[u*4+2] = hs[u*4+2] * dA + dtx * bb.z;
                hs[u*4+3] = hs[u*4+3] * dA + dtx * bb.w;
            }
#pragma unroll
            for (int u = 0; u < 4; u++) {
                float4 cc = *(const float4*)&sC[buf][t][u * 16 + ng * 4];
                yp += hs[u*4+0] * cc.x + hs[u*4+1] * cc.y
                    + hs[u*4+2] * cc.z + hs[u*4+3] * cc.w;
            }
            yv[t] = yp;
        }
#pragma unroll
        for (int t = 0; t < 8; t++) yv[t] += __shfl_xor_sync(0xffffffffu, yv[t], 1);
#pragma unroll
        for (int t = 0; t < 8; t++) yv[t] += __shfl_xor_sync(0xffffffffu, yv[t], 2);
        if (ng == 0) {
#pragma unroll
            for (int t = 0; t < 8; t++) {
                int l = LL - 1 - (s0 + t);
                yout[((size_t)(b * LL + l)) * DINNER + h * HEADD + pl] = yv[t];
            }
        }

        if (more) commit_smem(buf ^ 1);
        __syncthreads();
    }

    {
        float* hd = &g_hseg[((size_t)blk) * 4096 + pl * 64];
#pragma unroll
        for (int j = 0; j < 16; j++) {
            int n = ((j >> 2) << 4) + (ng << 2) + (j & 3);
            hd[n] = hs[j];
        }
    }
}

// ---------------- scan pass 2 ----------------
__global__ void __launch_bounds__(256)
scan_comb_kernel()
{
    int bh = blockIdx.x;
    int tid = threadIdx.x;
    float hst[16];
#pragma unroll
    for (int i = 0; i < 16; i++) hst[i] = 0.f;

    for (int seg = 0; seg < SSEG; seg++) {
        float P = g_cum[(size_t)bh * LL + seg * SEGL + SEGL - 1];
#pragma unroll
        for (int i = 0; i < 16; i++) {
            int e = tid + i * 256;
            size_t base = ((size_t)(bh * SSEG + seg)) * 4096 + e;
            g_hst[base] = hst[i];
            hst[i] = P * hst[i] + g_hseg[base];
        }
    }
}

// ---------------- scan pass 3 ----------------
__global__ void __launch_bounds__(256)
scan_fix_kernel(const float* __restrict__ xc, float* __restrict__ yout)
{
    int blk = blockIdx.x;
    int seg = blk & (SSEG - 1);
    if (seg == 0) return;
    int bh  = blk / SSEG;
    int b = bh >> 4, h = bh & 15;
    int tid = threadIdx.x;
    int pl = tid >> 2;
    int ng = tid & 3;

    float hs[16];
    {
        const float* hp = &g_hst[((size_t)blk) * 4096 + pl * 64];
#pragma unroll
        for (int j = 0; j < 16; j++) {
            int n = ((j >> 2) << 4) + (ng << 2) + (j & 3);
            hs[j] = hp[n];
        }
    }

    __shared__ float sC[8][64];
    __shared__ float sCum[8];
    const int sBeg = seg * SEGL;

    for (int s0 = sBeg; s0 < sBeg + SEGL; s0 += 8) {
#pragma unroll
        for (int i = 0; i < 2; i++) {
            int e = tid + i * 256;
            int t = e >> 6, q = e & 63;
            int bl = b * LL + (LL - 1 - (s0 + t));
            sC[t][q] = xc[(size_t)bl * CONVD + DINNER + DSTATE + q];
        }
        if (tid < 8) sCum[tid] = g_cum[(size_t)bh * LL + s0 + tid];
        __syncthreads();

        float yv[8];
#pragma unroll
        for (int t = 0; t < 8; t++) {
            float yp0 = 0.f, yp1 = 0.f, yp2 = 0.f, yp3 = 0.f;
#pragma unroll
            for (int u = 0; u < 4; u++) {
                float4 cc = *(const float4*)&sC[t][u * 16 + ng * 4];
                yp0 += hs[u*4+0] * cc.x;
                yp1 += hs[u*4+1] * cc.y;
                yp2 += hs[u*4+2] * cc.z;
                yp3 += hs[u*4+3] * cc.w;
            }
            yv[t] = ((yp0 + yp1) + (yp2 + yp3)) * sCum[t];
        }
#pragma unroll
        for (int t = 0; t < 8; t++) yv[t] += __shfl_xor_sync(0xffffffffu, yv[t], 1);
#pragma unroll
        for (int t = 0; t < 8; t++) yv[t] += __shfl_xor_sync(0xffffffffu, yv[t], 2);
        if (ng == 0) {
#pragma unroll
            for (int t = 0; t < 8; t++) {
                int l = LL - 1 - (s0 + t);
                size_t idx = ((size_t)(b * LL + l)) * DINNER + h * HEADD + pl;
                yout[idx] += yv[t];
            }
        }
        __syncthreads();
    }
}

// ---------------- block reduction helper ----------------
__device__ __forceinline__ float block_reduce_sum(float v) {
    __shared__ float sred[32];
    int lane = threadIdx.x & 31, w = threadIdx.x >> 5;
#pragma unroll
    for (int o = 16; o; o >>= 1) v += __shfl_xor_sync(0xffffffffu, v, o);
    if (lane == 0) sred[w] = v;
    __syncthreads();
    int nw = blockDim.x >> 5;
    float r = (threadIdx.x < nw) ? sred[threadIdx.x] : 0.f;
    if (w == 0) {
#pragma unroll
        for (int o = 16; o; o >>= 1) r += __shfl_xor_sync(0xffffffffu, r, o);
        if (lane == 0) sred[0] = r;
    }
    __syncthreads();
    float out = sred[0];
    __syncthreads();
    return out;
}

// ---------------- gate + rmsnorm -> split fp16 ----------------
__global__ void __launch_bounds__(256)
gate_rms_kernel(const float* __restrict__ ys, const float* __restrict__ xc,
                const float* __restrict__ zx, const float* __restrict__ Dv,
                const float* __restrict__ rw,
                __half* __restrict__ ybh, __half* __restrict__ ybl)
{
    int row = blockIdx.x;
    size_t oy = (size_t)row * DINNER, oc = (size_t)row * CONVD, oz = (size_t)row * NPROJ;
    float v[4];
    float ss = 0.f;
#pragma unroll
    for (int i = 0; i < 4; i++) {
        int c = threadIdx.x + i * 256;
        float z = zx[oz + c];
        float sz = z / (1.f + expf(-z));
        float val = (ys[oy + c] + Dv[c >> 6] * xc[oc + c]) * sz;
        v[i] = val;
        ss += val * val;
    }
    ss = block_reduce_sum(ss);
    float r = rsqrtf(ss * (1.f / (float)DINNER) + 1e-5f);
#pragma unroll
    for (int i = 0; i < 4; i++) {
        int c = threadIdx.x + i * 256;
        float val = v[i] * r * rw[c];
        __half hh = __float2half(val);
        ybh[oy + c] = hh;
        ybl[oy + c] = __float2half(val - __half2float(hh));
    }
}

// ---------------- layernorm -> split fp16 ----------------
__global__ void __launch_bounds__(128)
layernorm_kernel(const float* __restrict__ x, const float* __restrict__ g,
                 const float* __restrict__ bpar,
                 __half* __restrict__ oh, __half* __restrict__ ol)
{
    int row = blockIdx.x;
    size_t o = (size_t)row * DMODEL;
    float v[4];
    float s = 0.f;
#pragma unroll
    for (int i = 0; i < 4; i++) {
        int c = threadIdx.x + i * 128;
        v[i] = x[o + c];
        s += v[i];
    }
    s = block_reduce_sum(s);
    float m = s * (1.f / (float)DMODEL);
    float ss = 0.f;
#pragma unroll
    for (int i = 0; i < 4; i++) { float d = v[i] - m; ss += d * d; }
    ss = block_reduce_sum(ss);
    float r = rsqrtf(ss * (1.f / (float)DMODEL) + 1e-5f);
#pragma unroll
    for (int i = 0; i < 4; i++) {
        int c = threadIdx.x + i * 128;
        float val = (v[i] - m) * r * g[c] + bpar[c];
        __half hh = __float2half(val);
        oh[o + c] = hh;
        ol[o + c] = __float2half(val - __half2float(hh));
    }
}

// ---------------- launch ----------------
extern "C" void kernel_launch(void* const* d_in, const int* in_sizes, int n_in,
                              void* d_out, int out_size)
{
    const float* x         = (const float*)d_in[0];
    const float* in_proj_w = (const float*)d_in[1];
    const float* conv_w    = (const float*)d_in[2];
    const float* conv_b    = (const float*)d_in[3];
    const float* dt_bias   = (const float*)d_in[4];
    const float* A_log     = (const float*)d_in[5];
    const float* Dv        = (const float*)d_in[6];
    const float* rms_w     = (const float*)d_in[7];
    const float* out_proj  = (const float*)d_in[8];
    const float* ln_g      = (const float*)d_in[9];
    const float* ln_b      = (const float*)d_in[10];
    const float* w1        = (const float*)d_in[11];
    const float* b1        = (const float*)d_in[12];
    const float* w2        = (const float*)d_in[13];
    const float* b2        = (const float*)d_in[14];
    float* outp            = (float*)d_out;

    float *p_zx, *p_xc, *p_ys, *p_y2, *p_dt;
    cudaGetSymbolAddress((void**)&p_zx,  g_zx);
    cudaGetSymbolAddress((void**)&p_xc,  g_xc);
    cudaGetSymbolAddress((void**)&p_ys,  g_ys);
    cudaGetSymbolAddress((void**)&p_y2,  g_y2);
    cudaGetSymbolAddress((void**)&p_dt,  g_dt);

    __half *p_xhi, *p_xlo, *p_winh, *p_winl;
    __half *p_woh, *p_wol, *p_w1h, *p_w1l, *p_w2h, *p_w2l;
    __half *p_ybh, *p_ybl, *p_ylnh, *p_ylnl, *p_h1h, *p_h1l;
    cudaGetSymbolAddress((void**)&p_xhi,  g_xhi);
    cudaGetSymbolAddress((void**)&p_xlo,  g_xlo);
    cudaGetSymbolAddress((void**)&p_winh, g_winh);
    cudaGetSymbolAddress((void**)&p_winl, g_winl);
    cudaGetSymbolAddress((void**)&p_woh,  g_woh);
    cudaGetSymbolAddress((void**)&p_wol,  g_wol);
    cudaGetSymbolAddress((void**)&p_w1h,  g_w1h);
    cudaGetSymbolAddress((void**)&p_w1l,  g_w1l);
    cudaGetSymbolAddress((void**)&p_w2h,  g_w2h);
    cudaGetSymbolAddress((void**)&p_w2l,  g_w2l);
    cudaGetSymbolAddress((void**)&p_ybh,  g_ybh);
    cudaGetSymbolAddress((void**)&p_ybl,  g_ybl);
    cudaGetSymbolAddress((void**)&p_ylnh, g_ylnh);
    cudaGetSymbolAddress((void**)&p_ylnl, g_ylnl);
    cudaGetSymbolAddress((void**)&p_h1h,  g_h1h);
    cudaGetSymbolAddress((void**)&p_h1l,  g_h1l);

    static bool attr_done = false;
    if (!attr_done) {
        cudaFuncSetAttribute(hgemm2_kernel<0,0>, cudaFuncAttributeMaxDynamicSharedMemorySize, GSM_BYTES);
        cudaFuncSetAttribute(hgemm2_kernel<1,0>, cudaFuncAttributeMaxDynamicSharedMemorySize, GSM_BYTES);
        cudaFuncSetAttribute(hgemm2_kernel<2,1>, cudaFuncAttributeMaxDynamicSharedMemorySize, GSM_BYTES);
        attr_done = true;
    }

    // operand splitting (all fp16 now)
    {
        int n, tot;
        n = tot = BL * DMODEL;
        split_hf_kernel<<<(tot + 255) / 256, 256>>>(x, p_xhi, p_xlo, n, tot);
        n = NPROJ * DMODEL; tot = NPROJ_PAD * DMODEL;
        split_hf_kernel<<<(tot + 255) / 256, 256>>>(in_proj_w, p_winh, p_winl, n, tot);
        n = tot = DMODEL * DINNER;
        split_hf_kernel<<<(tot + 255) / 256, 256>>>(out_proj, p_woh, p_wol, n, tot);
        split_hf_kernel<<<(tot + 255) / 256, 256>>>(w2, p_w2h, p_w2l, n, tot);
        w1eff_split_kernel<<<(1024 * 512 + 255) / 256, 256>>>(w1, p_w1h, p_w1l);
    }
    // exact dt (fp32) — independent of in_proj GEMM
    dt_exact_kernel<<<BL, 128>>>(x, in_proj_w, p_dt);

    // 1) in_proj (fp16 2-pass)
    {
        dim3 grid(NPROJ_PAD / 128, BL / 128);
        hgemm2_kernel<0,0><<<grid, 256, GSM_BYTES>>>(p_xhi, p_xlo, p_winh,
                                                     nullptr, p_zx, nullptr, nullptr,
                                                     BL, NPROJ, DMODEL);
    }
    // 2) conv + silu
    {
        size_t tot = (size_t)BL * (CONVD / 4);
        conv_silu_kernel<<<(unsigned)((tot + 255) / 256), 256>>>(p_zx, conv_w, conv_b, p_xc);
    }
    // 3) segmented selective scan (dt from exact buffer)
    scan_seg1_kernel<<<64 * SSEG, 256>>>(p_dt, p_xc, dt_bias, A_log, p_ys);
    scan_comb_kernel<<<64, 256>>>();
    scan_fix_kernel<<<64 * SSEG, 256>>>(p_xc, p_ys);
    // 4) gate + rmsnorm -> fp16 split
    gate_rms_kernel<<<BL, 256>>>(p_ys, p_xc, p_zx, Dv, rms_w, p_ybh, p_ybl);
    // 5) out_proj (fp16 2-pass)
    {
        dim3 grid(DMODEL / 128, BL / 128);
        hgemm2_kernel<0,0><<<grid, 256, GSM_BYTES>>>(p_ybh, p_ybl, p_woh,
                                                     nullptr, p_y2, nullptr, nullptr,
                                                     BL, DMODEL, DINNER);
    }
    // 6) layernorm -> fp16 split
    layernorm_kernel<<<BL, 128>>>(p_y2, ln_g, ln_b, p_ylnh, p_ylnl);
    // 7) mlp hidden (fp16 2-pass, bias + silu, fp16-split out)
    {
        dim3 grid(DINNER / 128, BL / 128);
        hgemm2_kernel<2,1><<<grid, 256, GSM_BYTES>>>(p_ylnh, p_ylnl, p_w1h,
                                                     b1, nullptr, p_h1h, p_h1l,
                                                     BL, DINNER, DMODEL);
    }
    // 8) output (fp16 2-pass, bias)
    {
        dim3 grid(DMODEL / 128, BL / 128);
        hgemm2_kernel<1,0><<<grid, 256, GSM_BYTES>>>(p_h1h, p_h1l, p_w2h,
                                                     b2, outp, nullptr, nullptr,
                                                     BL, DMODEL, DINNER);
    }
}

// round 14
// speedup vs baseline: 1.1047x; 1.1047x over previous
#include <cuda_runtime.h>
#include <cuda_bf16.h>
#include <cuda_fp16.h>
#include <math.h>
#include <stdint.h>

// ---------------- problem constants ----------------
#define BB      4
#define LL      4096
#define DMODEL  512
#define DINNER  1024
#define DSTATE  64
#define HEADD   64
#define NHEADS  16
#define CONVD   1152
#define NPROJ   2192
#define NPROJ_PAD 2304      // 18*128
#define BL      (BB*LL)

// scan segmentation
#define SSEG    32
#define SEGL    (LL / SSEG)   // 128

// ---------------- scratch ----------------
__device__ float g_zx [(size_t)BL * NPROJ];
__device__ float g_xc [(size_t)BL * CONVD];
__device__ float g_ys [(size_t)BL * DINNER];
__device__ float g_y2 [(size_t)BL * DMODEL];
__device__ float g_hseg[64 * SSEG * 4096];
__device__ float g_hst [64 * SSEG * 4096];
__device__ float g_cum [64 * LL];

// pre-split operands: bf16 for in_proj, fp16 for the rest
__device__ __nv_bfloat16 g_xhi [(size_t)BL * DMODEL],  g_xlo [(size_t)BL * DMODEL];
__device__ __nv_bfloat16 g_winh[(size_t)NPROJ_PAD * DMODEL], g_winl[(size_t)NPROJ_PAD * DMODEL];
__device__ __half g_woh [DMODEL * DINNER], g_wol [DMODEL * DINNER];
__device__ __half g_w1h [DINNER * DMODEL], g_w1l [DINNER * DMODEL];
__device__ __half g_w2h [DMODEL * DINNER], g_w2l [DMODEL * DINNER];
__device__ __half g_ybh [(size_t)BL * DINNER], g_ybl [(size_t)BL * DINNER];
__device__ __half g_ylnh[(size_t)BL * DMODEL], g_ylnl[(size_t)BL * DMODEL];
__device__ __half g_h1h [(size_t)BL * DINNER], g_h1l [(size_t)BL * DINNER];

// ================= helpers =================
__device__ __forceinline__ unsigned pack16(unsigned short a, unsigned short b) {
    return (unsigned)a | ((unsigned)b << 16);
}
__device__ __forceinline__ void ldsm_x4(unsigned &r0, unsigned &r1,
                                        unsigned &r2, unsigned &r3, unsigned addr) {
    asm volatile("ldmatrix.sync.aligned.m8n8.x4.shared.b16 {%0,%1,%2,%3}, [%4];"
                 : "=r"(r0), "=r"(r1), "=r"(r2), "=r"(r3) : "r"(addr));
}
__device__ __forceinline__ void mma_bf(float* c, const unsigned* a, const unsigned* b) {
    asm volatile(
        "mma.sync.aligned.m16n8k16.row.col.f32.bf16.bf16.f32 "
        "{%0,%1,%2,%3}, {%4,%5,%6,%7}, {%8,%9}, {%0,%1,%2,%3};"
        : "+f"(c[0]), "+f"(c[1]), "+f"(c[2]), "+f"(c[3])
        : "r"(a[0]), "r"(a[1]), "r"(a[2]), "r"(a[3]), "r"(b[0]), "r"(b[1]));
}
__device__ __forceinline__ void mma_hf(float* c, const unsigned* a, const unsigned* b) {
    asm volatile(
        "mma.sync.aligned.m16n8k16.row.col.f32.f16.f16.f32 "
        "{%0,%1,%2,%3}, {%4,%5,%6,%7}, {%8,%9}, {%0,%1,%2,%3};"
        : "+f"(c[0]), "+f"(c[1]), "+f"(c[2]), "+f"(c[3])
        : "r"(a[0]), "r"(a[1]), "r"(a[2]), "r"(a[3]), "r"(b[0]), "r"(b[1]));
}
__device__ __forceinline__ void cp16(unsigned dst, const void* src) {
    asm volatile("cp.async.cg.shared.global [%0], [%1], 16;" :: "r"(dst), "l"(src));
}

#define TILE_BYTES   16384
#define BUF_BYTES    (2 * TILE_BYTES)
#define GSM_BYTES    (2 * BUF_BYTES)   // 64KB, 2-stage

// ================= GEMM: C = A @ W^T, pre-split hi/lo, 2-stage pipeline ==========
// H=0: bf16 3-pass (AhBh+AhBl+AlBh).  H=1: fp16 2-pass (AhBh+AlBh, no Bl).
template<int EPI, int OSPLIT, int H>
__global__ void __launch_bounds__(256, 2)
hgemm3_kernel(const void* __restrict__ Ahi_, const void* __restrict__ Alo_,
              const void* __restrict__ Whi_, const void* __restrict__ Wlo_,
              const float* __restrict__ bias, float* __restrict__ C,
              __half* __restrict__ Chi, __half* __restrict__ Clo,
              int M, int N, int K)
{
    const unsigned short* Ahi = (const unsigned short*)Ahi_;
    const unsigned short* Alo = (const unsigned short*)Alo_;
    const unsigned short* Whi = (const unsigned short*)Whi_;
    const unsigned short* Wlo = (const unsigned short*)Wlo_;

    extern __shared__ char smem[];

    const int tid  = threadIdx.x;
    const int lane = tid & 31;
    const int wid  = tid >> 5;
    const int wm   = wid & 1;
    const int wn   = wid >> 1;
    const int m0   = blockIdx.y * 128;
    const int n0   = blockIdx.x * 128;

    const int lrow = tid >> 1;
    const int half = tid & 1;
    const int rsw  = lrow & 7;
    const int c0 = 2 * half, c1 = 2 * half + 1, c2 = 4 + 2 * half, c3 = 5 + 2 * half;

    const unsigned s_u32 = (unsigned)__cvta_generic_to_shared(&smem[0]);
    const unsigned abase = s_u32 + (unsigned)(lrow * 128);
    const unsigned bbase = s_u32 + (unsigned)(TILE_BYTES + lrow * 128);

    unsigned aBase[4]; int aSw[4];
    const int kcA = lane >> 4;
#pragma unroll
    for (int mi = 0; mi < 4; mi++) {
        int r = wm * 64 + mi * 16 + (lane & 7) + ((lane >> 3) & 1) * 8;
        aBase[mi] = s_u32 + (unsigned)(r * 128);
        aSw[mi] = r & 7;
    }
    unsigned bBase[2]; int bSw[2];
    const int kcB = (lane >> 3) & 1;
#pragma unroll
    for (int pj = 0; pj < 2; pj++) {
        int r = wn * 32 + pj * 16 + ((lane >> 4) & 1) * 8 + (lane & 7);
        bBase[pj] = s_u32 + (unsigned)(TILE_BYTES + r * 128);
        bSw[pj] = r & 7;
    }

    float acc[4][4][4];
#pragma unroll
    for (int i = 0; i < 4; i++)
#pragma unroll
        for (int j = 0; j < 4; j++)
#pragma unroll
            for (int q = 0; q < 4; q++) acc[i][j][q] = 0.f;

    auto issue = [&](int k0, int buf) {
        unsigned bo = (unsigned)(buf * BUF_BYTES);
        const unsigned short* sa  = Ahi + (size_t)(m0 + lrow) * K + k0 + half * 16;
        const unsigned short* sal = Alo + (size_t)(m0 + lrow) * K + k0 + half * 16;
        const unsigned short* sb  = Whi + (size_t)(n0 + lrow) * K + k0 + half * 16;
        cp16(abase + bo + (unsigned)((c0 ^ rsw) * 16), sa);
        cp16(abase + bo + (unsigned)((c1 ^ rsw) * 16), sa + 8);
        cp16(abase + bo + (unsigned)((c2 ^ rsw) * 16), sal);
        cp16(abase + bo + (unsigned)((c3 ^ rsw) * 16), sal + 8);
        cp16(bbase + bo + (unsigned)((c0 ^ rsw) * 16), sb);
        cp16(bbase + bo + (unsigned)((c1 ^ rsw) * 16), sb + 8);
        if (!H) {
            const unsigned short* sbl = Wlo + (size_t)(n0 + lrow) * K + k0 + half * 16;
            cp16(bbase + bo + (unsigned)((c2 ^ rsw) * 16), sbl);
            cp16(bbase + bo + (unsigned)((c3 ^ rsw) * 16), sbl + 8);
        }
        asm volatile("cp.async.commit_group;" ::: "memory");
    };

    auto MMA = [&](float* c, const unsigned* a, const unsigned* b) {
        if (H) mma_hf(c, a, b); else mma_bf(c, a, b);
    };

    auto do_ks = [&](int ks, unsigned boff) {
        unsigned bh[4][2];
#pragma unroll
        for (int pj = 0; pj < 2; pj++) {
            unsigned r0, r1, r2, r3;
            ldsm_x4(r0, r1, r2, r3,
                    bBase[pj] + boff + (unsigned)((((ks * 2 + kcB)) ^ bSw[pj]) * 16));
            bh[pj * 2][0] = r0; bh[pj * 2][1] = r1;
            bh[pj * 2 + 1][0] = r2; bh[pj * 2 + 1][1] = r3;
        }
        if (!H) {
            unsigned bt[4][2];
#pragma unroll
            for (int pj = 0; pj < 2; pj++) {
                unsigned r0, r1, r2, r3;
                ldsm_x4(r0, r1, r2, r3,
                        bBase[pj] + boff + (unsigned)((((ks * 2 + kcB + 4)) ^ bSw[pj]) * 16));
                bt[pj * 2][0] = r0; bt[pj * 2][1] = r1;
                bt[pj * 2 + 1][0] = r2; bt[pj * 2 + 1][1] = r3;
            }
#pragma unroll
            for (int mi = 0; mi < 4; mi++) {
                unsigned a[4];
                ldsm_x4(a[0], a[1], a[2], a[3],
                        aBase[mi] + boff + (unsigned)((((ks * 2 + kcA)) ^ aSw[mi]) * 16));
#pragma unroll
                for (int nj = 0; nj < 4; nj++) MMA(acc[mi][nj], a, bh[nj]);
#pragma unroll
                for (int nj = 0; nj < 4; nj++) MMA(acc[mi][nj], a, bt[nj]);
                ldsm_x4(a[0], a[1], a[2], a[3],
                        aBase[mi] + boff + (unsigned)((((ks * 2 + kcA + 4)) ^ aSw[mi]) * 16));
#pragma unroll
                for (int nj = 0; nj < 4; nj++) MMA(acc[mi][nj], a, bh[nj]);
            }
        } else {
#pragma unroll
            for (int mi = 0; mi < 4; mi++) {
                unsigned a[4];
                ldsm_x4(a[0], a[1], a[2], a[3],
                        aBase[mi] + boff + (unsigned)((((ks * 2 + kcA)) ^ aSw[mi]) * 16));
#pragma unroll
                for (int nj = 0; nj < 4; nj++) MMA(acc[mi][nj], a, bh[nj]);
                ldsm_x4(a[0], a[1], a[2], a[3],
                        aBase[mi] + boff + (unsigned)((((ks * 2 + kcA + 4)) ^ aSw[mi]) * 16));
#pragma unroll
                for (int nj = 0; nj < 4; nj++) MMA(acc[mi][nj], a, bh[nj]);
            }
        }
    };

    issue(0, 0);
    const int nk = K >> 5;
    for (int it = 0; it < nk; it++) {
        asm volatile("cp.async.wait_group 0;" ::: "memory");
        __syncthreads();
        if (it + 1 < nk) issue((it + 1) * 32, (it + 1) & 1);
        const unsigned boff = (unsigned)((it & 1) * BUF_BYTES);
        do_ks(0, boff);
        do_ks(1, boff);
    }

    // epilogue
    const int row0 = m0 + wm * 64 + (lane >> 2);
    const int col0 = n0 + wn * 32 + (lane & 3) * 2;
#pragma unroll
    for (int mi = 0; mi < 4; mi++) {
#pragma unroll
        for (int nj = 0; nj < 4; nj++) {
            int col = col0 + nj * 8;
            if (col < N) {
                float b0 = 0.f, b1 = 0.f;
                if (EPI >= 1) { b0 = bias[col]; b1 = bias[col + 1]; }
                float v0 = acc[mi][nj][0] + b0;
                float v1 = acc[mi][nj][1] + b1;
                float v2 = acc[mi][nj][2] + b0;
                float v3 = acc[mi][nj][3] + b1;
                if (EPI == 2) {
                    v0 = v0 / (1.f + expf(-v0));
                    v1 = v1 / (1.f + expf(-v1));
                    v2 = v2 / (1.f + expf(-v2));
                    v3 = v3 / (1.f + expf(-v3));
                }
                int r = row0 + mi * 16;
                if (OSPLIT) {
                    __half h0 = __float2half(v0), h1 = __float2half(v1);
                    __half h2 = __float2half(v2), h3 = __float2half(v3);
                    __half l0 = __float2half(v0 - __half2float(h0));
                    __half l1 = __float2half(v1 - __half2float(h1));
                    __half l2 = __float2half(v2 - __half2float(h2));
                    __half l3 = __float2half(v3 - __half2float(h3));
                    *(unsigned*)&Chi[(size_t)r * N + col]       = pack16(*(unsigned short*)&h0, *(unsigned short*)&h1);
                    *(unsigned*)&Clo[(size_t)r * N + col]       = pack16(*(unsigned short*)&l0, *(unsigned short*)&l1);
                    *(unsigned*)&Chi[(size_t)(r + 8) * N + col] = pack16(*(unsigned short*)&h2, *(unsigned short*)&h3);
                    *(unsigned*)&Clo[(size_t)(r + 8) * N + col] = pack16(*(unsigned short*)&l2, *(unsigned short*)&l3);
                } else {
                    float2 p0; p0.x = v0; p0.y = v1;
                    float2 p1; p1.x = v2; p1.y = v3;
                    *(float2*)&C[(size_t)r * N + col] = p0;
                    *(float2*)&C[(size_t)(r + 8) * N + col] = p1;
                }
            }
        }
    }
}

// ---------------- vectorized splits (4 elems/thread) ----------------
__global__ void __launch_bounds__(256)
split_bf4_kernel(const float* __restrict__ src, __nv_bfloat16* __restrict__ hi,
                 __nv_bfloat16* __restrict__ lo, int n, int total4)
{
    int i4 = blockIdx.x * blockDim.x + threadIdx.x;
    if (i4 >= total4) return;
    int base = i4 * 4;
    float v[4];
#pragma unroll
    for (int j = 0; j < 4; j++) v[j] = (base + j < n) ? src[base + j] : 0.f;
    unsigned short h[4], l[4];
#pragma unroll
    for (int j = 0; j < 4; j++) {
        __nv_bfloat16 hb = __float2bfloat16(v[j]);
        __nv_bfloat16 lb = __float2bfloat16(v[j] - __bfloat162float(hb));
        h[j] = *(unsigned short*)&hb;
        l[j] = *(unsigned short*)&lb;
    }
    uint2 ho; ho.x = pack16(h[0], h[1]); ho.y = pack16(h[2], h[3]);
    uint2 lv; lv.x = pack16(l[0], l[1]); lv.y = pack16(l[2], l[3]);
    *(uint2*)&hi[base] = ho;
    *(uint2*)&lo[base] = lv;
}
__global__ void __launch_bounds__(256)
split_hf4_kernel(const float* __restrict__ src, __half* __restrict__ hi,
                 __half* __restrict__ lo, int total4)
{
    int i4 = blockIdx.x * blockDim.x + threadIdx.x;
    if (i4 >= total4) return;
    int base = i4 * 4;
    float4 v = *(const float4*)&src[base];
    float f[4] = {v.x, v.y, v.z, v.w};
    unsigned short h[4], l[4];
#pragma unroll
    for (int j = 0; j < 4; j++) {
        __half hb = __float2half(f[j]);
        __half lb = __float2half(f[j] - __half2float(hb));
        h[j] = *(unsigned short*)&hb;
        l[j] = *(unsigned short*)&lb;
    }
    uint2 ho; ho.x = pack16(h[0], h[1]); ho.y = pack16(h[2], h[3]);
    uint2 lv; lv.x = pack16(l[0], l[1]); lv.y = pack16(l[2], l[3]);
    *(uint2*)&hi[base] = ho;
    *(uint2*)&lo[base] = lv;
}
__global__ void __launch_bounds__(256)
w1eff_split_kernel(const float* __restrict__ w1, __half* __restrict__ hi,
                   __half* __restrict__ lo)
{
    int i4 = blockIdx.x * blockDim.x + threadIdx.x;
    if (i4 >= 1024 * 512 / 4) return;
    int base = i4 * 4;
    int n = base / 512, k = base % 512;
    float4 a = *(const float4*)&w1[n * 1024 + k];
    float4 b = *(const float4*)&w1[n * 1024 + 512 + k];
    float f[4] = {a.x + b.x, a.y + b.y, a.z + b.z, a.w + b.w};
    unsigned short h[4], l[4];
#pragma unroll
    for (int j = 0; j < 4; j++) {
        __half hb = __float2half(f[j]);
        __half lb = __float2half(f[j] - __half2float(hb));
        h[j] = *(unsigned short*)&hb;
        l[j] = *(unsigned short*)&lb;
    }
    uint2 ho; ho.x = pack16(h[0], h[1]); ho.y = pack16(h[2], h[3]);
    uint2 lv; lv.x = pack16(l[0], l[1]); lv.y = pack16(l[2], l[3]);
    *(uint2*)&hi[base] = ho;
    *(uint2*)&lo[base] = lv;
}

// ---------------- conv (anti-causal) + silu, float4 vectorized ----------------
__global__ void __launch_bounds__(256)
conv_silu_kernel(const float* __restrict__ zx, const float* __restrict__ cw,
                 const float* __restrict__ cb, float* __restrict__ xc)
{
    size_t idx = (size_t)blockIdx.x * blockDim.x + threadIdx.x;
    if (idx >= (size_t)BL * (CONVD / 4)) return;
    int c4 = (int)(idx % (CONVD / 4));
    int bl = (int)(idx / (CONVD / 4));
    int l  = bl % LL;
    int c  = c4 * 4;

    float4 acc = *(const float4*)&cb[c];
    float4 w0 = *(const float4*)&cw[c * 4 + 0];
    float4 w1 = *(const float4*)&cw[c * 4 + 4];
    float4 w2 = *(const float4*)&cw[c * 4 + 8];
    float4 w3 = *(const float4*)&cw[c * 4 + 12];

    const float* base = zx + (size_t)bl * NPROJ + DINNER + c;
#pragma unroll
    for (int k = 0; k < 4; k++) {
        int off = 3 - k;
        if (l + off < LL) {
            float4 v = *(const float4*)(base + (size_t)off * NPROJ);
            acc.x += ((const float*)&w0)[k] * v.x;
            acc.y += ((const float*)&w1)[k] * v.y;
            acc.z += ((const float*)&w2)[k] * v.z;
            acc.w += ((const float*)&w3)[k] * v.w;
        }
    }
    acc.x = acc.x / (1.f + expf(-acc.x));
    acc.y = acc.y / (1.f + expf(-acc.y));
    acc.z = acc.z / (1.f + expf(-acc.z));
    acc.w = acc.w / (1.f + expf(-acc.w));
    *(float4*)&xc[(size_t)bl * CONVD + c] = acc;
}

// ---------------- scan pass 1 ----------------
__global__ void __launch_bounds__(256)
scan_seg1_kernel(const float* __restrict__ zx, const float* __restrict__ xc,
                 const float* __restrict__ dt_bias, const float* __restrict__ A_log,
                 float* __restrict__ yout)
{
    int blk = blockIdx.x;
    int seg = blk & (SSEG - 1);
    int bh  = blk / SSEG;
    int b = bh >> 4, h = bh & 15;
    int tid = threadIdx.x;
    int pl = tid >> 2;
    int ng = tid & 3;

    float Acoef = -expf(A_log[h]);
    float dtb   = dt_bias[h];

    __shared__ float sB[2][8][64], sC[2][8][64], sX[2][8][64];
    __shared__ float sdt[2][8], sDA[2][8];

    float hs[16];
#pragma unroll
    for (int j = 0; j < 16; j++) hs[j] = 0.f;

    float rBC[4], rX[2], rDR = 0.f;
    const int sBeg = seg * SEGL;
    const int sEnd = sBeg + SEGL;

    float runP = 1.f;

    auto preload = [&](int s0) {
#pragma unroll
        for (int i = 0; i < 4; i++) {
            int e = tid + i * 256;
            int t = e >> 7, q = e & 127;
            int bl = b * LL + (LL - 1 - (s0 + t));
            rBC[i] = xc[(size_t)bl * CONVD + DINNER + q];
        }
#pragma unroll
        for (int i = 0; i < 2; i++) {
            int e = tid + i * 256;
            int t = e >> 6, j = e & 63;
            int bl = b * LL + (LL - 1 - (s0 + t));
            rX[i] = xc[(size_t)bl * CONVD + h * HEADD + j];
        }
        if (tid < 8) {
            int bl = b * LL + (LL - 1 - (s0 + tid));
            rDR = zx[(size_t)bl * NPROJ + (2 * DINNER + 2 * DSTATE) + h];
        }
    };
    auto commit_smem = [&](int buf) {
#pragma unroll
        for (int i = 0; i < 4; i++) {
            int e = tid + i * 256;
            int t = e >> 7, q = e & 127;
            if (q < 64) sB[buf][t][q] = rBC[i]; else sC[buf][t][q - 64] = rBC[i];
        }
#pragma unroll
        for (int i = 0; i < 2; i++) {
            int e = tid + i * 256;
            int t = e >> 6, j = e & 63;
            sX[buf][t][j] = rX[i];
        }
        if (tid < 8) {
            float dr = rDR + dtb;
            float dt = (dr > 20.f) ? dr : log1pf(expf(dr));
            sdt[buf][tid] = dt;
            sDA[buf][tid] = expf(dt * Acoef);
        }
    };

    preload(sBeg);
    commit_smem(0);
    __syncthreads();

    for (int s0 = sBeg; s0 < sEnd; s0 += 8) {
        int buf = ((s0 - sBeg) >> 3) & 1;
        bool more = (s0 + 8) < sEnd;
        if (more) preload(s0 + 8);

        if (tid == 0) {
            float* cw = &g_cum[(size_t)bh * LL + s0];
#pragma unroll
            for (int t = 0; t < 8; t++) { runP *= sDA[buf][t]; cw[t] = runP; }
        }

        float yv[8];
#pragma unroll
        for (int t = 0; t < 8; t++) {
            float dA  = sDA[buf][t];
            float dtx = sdt[buf][t] * sX[buf][t][pl];
            float yp = 0.f;
#pragma unroll
            for (int u = 0; u < 4; u++) {
                float4 bb = *(const float4*)&sB[buf][t][u * 16 + ng * 4];
                hs[u*4+0] = hs[u*4+0] * dA + dtx * bb.x;
                hs[u*4+1] = hs[u*4+1] * dA + dtx * bb.y;
                hs[u*4+2] = hs[u*4+2] * dA + dtx * bb.z;
                hs[u*4+3] = hs[u*4+3] * dA + dtx * bb.w;
            }
#pragma unroll
            for (int u = 0; u < 4; u++) {
                float4 cc = *(const float4*)&sC[buf][t][u * 16 + ng * 4];
                yp += hs[u*4+0] * cc.x + hs[u*4+1] * cc.y
                    + hs[u*4+2] * cc.z + hs[u*4+3] * cc.w;
            }
            yv[t] = yp;
        }
#pragma unroll
        for (int t = 0; t < 8; t++) yv[t] += __shfl_xor_sync(0xffffffffu, yv[t], 1);
#pragma unroll
        for (int t = 0; t < 8; t++) yv[t] += __shfl_xor_sync(0xffffffffu, yv[t], 2);
        if (ng == 0) {
#pragma unroll
            for (int t = 0; t < 8; t++) {
                int l = LL - 1 - (s0 + t);
                yout[((size_t)(b * LL + l)) * DINNER + h * HEADD + pl] = yv[t];
            }
        }

        if (more) commit_smem(buf ^ 1);
        __syncthreads();
    }

    {
        float* hd = &g_hseg[((size_t)blk) * 4096 + pl * 64];
#pragma unroll
        for (int j = 0; j < 16; j++) {
            int n = ((j >> 2) << 4) + (ng << 2) + (j & 3);
            hd[n] = hs[j];
        }
    }
}

// ---------------- scan pass 2 ----------------
__global__ void __launch_bounds__(256)
scan_comb_kernel()
{
    int bh = blockIdx.x;
    int tid = threadIdx.x;
    float hst[16];
#pragma unroll
    for (int i = 0; i < 16; i++) hst[i] = 0.f;

    for (int seg = 0; seg < SSEG; seg++) {
        float P = g_cum[(size_t)bh * LL + seg * SEGL + SEGL - 1];
#pragma unroll
        for (int i = 0; i < 16; i++) {
            int e = tid + i * 256;
            size_t base = ((size_t)(bh * SSEG + seg)) * 4096 + e;
            g_hst[base] = hst[i];
            hst[i] = P * hst[i] + g_hseg[base];
        }
    }
}

// ---------------- scan pass 3 ----------------
__global__ void __launch_bounds__(256)
scan_fix_kernel(const float* __restrict__ xc, float* __restrict__ yout)
{
    int blk = blockIdx.x;
    int seg = blk & (SSEG - 1);
    if (seg == 0) return;
    int bh  = blk / SSEG;
    int b = bh >> 4, h = bh & 15;
    int tid = threadIdx.x;
    int pl = tid >> 2;
    int ng = tid & 3;

    float hs[16];
    {
        const float* hp = &g_hst[((size_t)blk) * 4096 + pl * 64];
#pragma unroll
        for (int j = 0; j < 16; j++) {
            int n = ((j >> 2) << 4) + (ng << 2) + (j & 3);
            hs[j] = hp[n];
        }
    }

    __shared__ float sC[8][64];
    __shared__ float sCum[8];
    const int sBeg = seg * SEGL;

    for (int s0 = sBeg; s0 < sBeg + SEGL; s0 += 8) {
#pragma unroll
        for (int i = 0; i < 2; i++) {
            int e = tid + i * 256;
            int t = e >> 6, q = e & 63;
            int bl = b * LL + (LL - 1 - (s0 + t));
            sC[t][q] = xc[(size_t)bl * CONVD + DINNER + DSTATE + q];
        }
        if (tid < 8) sCum[tid] = g_cum[(size_t)bh * LL + s0 + tid];
        __syncthreads();

        float yv[8];
#pragma unroll
        for (int t = 0; t < 8; t++) {
            float yp0 = 0.f, yp1 = 0.f, yp2 = 0.f, yp3 = 0.f;
#pragma unroll
            for (int u = 0; u < 4; u++) {
                float4 cc = *(const float4*)&sC[t][u * 16 + ng * 4];
                yp0 += hs[u*4+0] * cc.x;
                yp1 += hs[u*4+1] * cc.y;
                yp2 += hs[u*4+2] * cc.z;
                yp3 += hs[u*4+3] * cc.w;
            }
            yv[t] = ((yp0 + yp1) + (yp2 + yp3)) * sCum[t];
        }
#pragma unroll
        for (int t = 0; t < 8; t++) yv[t] += __shfl_xor_sync(0xffffffffu, yv[t], 1);
#pragma unroll
        for (int t = 0; t < 8; t++) yv[t] += __shfl_xor_sync(0xffffffffu, yv[t], 2);
        if (ng == 0) {
#pragma unroll
            for (int t = 0; t < 8; t++) {
                int l = LL - 1 - (s0 + t);
                size_t idx = ((size_t)(b * LL + l)) * DINNER + h * HEADD + pl;
                yout[idx] += yv[t];
            }
        }
        __syncthreads();
    }
}

// ---------------- block reduction helper ----------------
__device__ __forceinline__ float block_reduce_sum(float v) {
    __shared__ float sred[32];
    int lane = threadIdx.x & 31, w = threadIdx.x >> 5;
#pragma unroll
    for (int o = 16; o; o >>= 1) v += __shfl_xor_sync(0xffffffffu, v, o);
    if (lane == 0) sred[w] = v;
    __syncthreads();
    int nw = blockDim.x >> 5;
    float r = (threadIdx.x < nw) ? sred[threadIdx.x] : 0.f;
    if (w == 0) {
#pragma unroll
        for (int o = 16; o; o >>= 1) r += __shfl_xor_sync(0xffffffffu, r, o);
        if (lane == 0) sred[0] = r;
    }
    __syncthreads();
    float out = sred[0];
    __syncthreads();
    return out;
}

// ---------------- gate + rmsnorm -> split fp16 (vectorized) ----------------
__global__ void __launch_bounds__(256)
gate_rms_kernel(const float* __restrict__ ys, const float* __restrict__ xc,
                const float* __restrict__ zx, const float* __restrict__ Dv,
                const float* __restrict__ rw,
                __half* __restrict__ ybh, __half* __restrict__ ybl)
{
    int row = blockIdx.x;
    int c = threadIdx.x * 4;
    size_t oy = (size_t)row * DINNER, oc = (size_t)row * CONVD, oz = (size_t)row * NPROJ;
    float4 yv = *(const float4*)&ys[oy + c];
    float4 xv = *(const float4*)&xc[oc + c];
    float4 zv = *(const float4*)&zx[oz + c];
    float Dh = Dv[c >> 6];
    float v[4];
    {
        float z[4] = {zv.x, zv.y, zv.z, zv.w};
        float yy[4] = {yv.x, yv.y, yv.z, yv.w};
        float xx[4] = {xv.x, xv.y, xv.z, xv.w};
#pragma unroll
        for (int j = 0; j < 4; j++) {
            float sz = z[j] / (1.f + expf(-z[j]));
            v[j] = (yy[j] + Dh * xx[j]) * sz;
        }
    }
    float ss = v[0]*v[0] + v[1]*v[1] + v[2]*v[2] + v[3]*v[3];
    ss = block_reduce_sum(ss);
    float r = rsqrtf(ss * (1.f / (float)DINNER) + 1e-5f);
    float4 rwv = *(const float4*)&rw[c];
    float rr[4] = {rwv.x, rwv.y, rwv.z, rwv.w};
    unsigned short h[4], l[4];
#pragma unroll
    for (int j = 0; j < 4; j++) {
        float val = v[j] * r * rr[j];
        __half hh = __float2half(val);
        __half ll = __float2half(val - __half2float(hh));
        h[j] = *(unsigned short*)&hh;
        l[j] = *(unsigned short*)&ll;
    }
    uint2 ho; ho.x = pack16(h[0], h[1]); ho.y = pack16(h[2], h[3]);
    uint2 lo; lo.x = pack16(l[0], l[1]); lo.y = pack16(l[2], l[3]);
    *(uint2*)&ybh[oy + c] = ho;
    *(uint2*)&ybl[oy + c] = lo;
}

// ---------------- layernorm -> split fp16 (vectorized) ----------------
__global__ void __launch_bounds__(128)
layernorm_kernel(const float* __restrict__ x, const float* __restrict__ g,
                 const float* __restrict__ bpar,
                 __half* __restrict__ oh, __half* __restrict__ ol)
{
    int row = blockIdx.x;
    int c = threadIdx.x * 4;
    size_t o = (size_t)row * DMODEL;
    float4 xv = *(const float4*)&x[o + c];
    float v[4] = {xv.x, xv.y, xv.z, xv.w};
    float s = v[0] + v[1] + v[2] + v[3];
    s = block_reduce_sum(s);
    float m = s * (1.f / (float)DMODEL);
    float ss = 0.f;
#pragma unroll
    for (int j = 0; j < 4; j++) { float d = v[j] - m; ss += d * d; }
    ss = block_reduce_sum(ss);
    float r = rsqrtf(ss * (1.f / (float)DMODEL) + 1e-5f);
    float4 gv = *(const float4*)&g[c];
    float4 bv = *(const float4*)&bpar[c];
    float gg[4] = {gv.x, gv.y, gv.z, gv.w};
    float bb[4] = {bv.x, bv.y, bv.z, bv.w};
    unsigned short h[4], l[4];
#pragma unroll
    for (int j = 0; j < 4; j++) {
        float val = (v[j] - m) * r * gg[j] + bb[j];
        __half hh = __float2half(val);
        __half ll = __float2half(val - __half2float(hh));
        h[j] = *(unsigned short*)&hh;
        l[j] = *(unsigned short*)&ll;
    }
    uint2 ho; ho.x = pack16(h[0], h[1]); ho.y = pack16(h[2], h[3]);
    uint2 lo; lo.x = pack16(l[0], l[1]); lo.y = pack16(l[2], l[3]);
    *(uint2*)&oh[o + c] = ho;
    *(uint2*)&ol[o + c] = lo;
}

// ---------------- launch ----------------
extern "C" void kernel_launch(void* const* d_in, const int* in_sizes, int n_in,
                              void* d_out, int out_size)
{
    const float* x         = (const float*)d_in[0];
    const float* in_proj_w = (const float*)d_in[1];
    const float* conv_w    = (const float*)d_in[2];
    const float* conv_b    = (const float*)d_in[3];
    const float* dt_bias   = (const float*)d_in[4];
    const float* A_log     = (const float*)d_in[5];
    const float* Dv        = (const float*)d_in[6];
    const float* rms_w     = (const float*)d_in[7];
    const float* out_proj  = (const float*)d_in[8];
    const float* ln_g      = (const float*)d_in[9];
    const float* ln_b      = (const float*)d_in[10];
    const float* w1        = (const float*)d_in[11];
    const float* b1        = (const float*)d_in[12];
    const float* w2        = (const float*)d_in[13];
    const float* b2        = (const float*)d_in[14];
    float* outp            = (float*)d_out;

    float *p_zx, *p_xc, *p_ys, *p_y2;
    cudaGetSymbolAddress((void**)&p_zx,  g_zx);
    cudaGetSymbolAddress((void**)&p_xc,  g_xc);
    cudaGetSymbolAddress((void**)&p_ys,  g_ys);
    cudaGetSymbolAddress((void**)&p_y2,  g_y2);

    __nv_bfloat16 *p_xhi, *p_xlo, *p_winh, *p_winl;
    __half *p_woh, *p_wol, *p_w1h, *p_w1l, *p_w2h, *p_w2l;
    __half *p_ybh, *p_ybl, *p_ylnh, *p_ylnl, *p_h1h, *p_h1l;
    cudaGetSymbolAddress((void**)&p_xhi,  g_xhi);
    cudaGetSymbolAddress((void**)&p_xlo,  g_xlo);
    cudaGetSymbolAddress((void**)&p_winh, g_winh);
    cudaGetSymbolAddress((void**)&p_winl, g_winl);
    cudaGetSymbolAddress((void**)&p_woh,  g_woh);
    cudaGetSymbolAddress((void**)&p_wol,  g_wol);
    cudaGetSymbolAddress((void**)&p_w1h,  g_w1h);
    cudaGetSymbolAddress((void**)&p_w1l,  g_w1l);
    cudaGetSymbolAddress((void**)&p_w2h,  g_w2h);
    cudaGetSymbolAddress((void**)&p_w2l,  g_w2l);
    cudaGetSymbolAddress((void**)&p_ybh,  g_ybh);
    cudaGetSymbolAddress((void**)&p_ybl,  g_ybl);
    cudaGetSymbolAddress((void**)&p_ylnh, g_ylnh);
    cudaGetSymbolAddress((void**)&p_ylnl, g_ylnl);
    cudaGetSymbolAddress((void**)&p_h1h,  g_h1h);
    cudaGetSymbolAddress((void**)&p_h1l,  g_h1l);

    static bool attr_done = false;
    if (!attr_done) {
        cudaFuncSetAttribute(hgemm3_kernel<0,0,0>, cudaFuncAttributeMaxDynamicSharedMemorySize, GSM_BYTES);
        cudaFuncSetAttribute(hgemm3_kernel<0,0,1>, cudaFuncAttributeMaxDynamicSharedMemorySize, GSM_BYTES);
        cudaFuncSetAttribute(hgemm3_kernel<1,0,1>, cudaFuncAttributeMaxDynamicSharedMemorySize, GSM_BYTES);
        cudaFuncSetAttribute(hgemm3_kernel<2,1,1>, cudaFuncAttributeMaxDynamicSharedMemorySize, GSM_BYTES);
        attr_done = true;
    }

    // operand splitting (vectorized)
    {
        int n, tot4;
        n = BL * DMODEL; tot4 = n / 4;
        split_bf4_kernel<<<(tot4 + 255) / 256, 256>>>(x, p_xhi, p_xlo, n, tot4);
        n = NPROJ * DMODEL; tot4 = NPROJ_PAD * DMODEL / 4;
        split_bf4_kernel<<<(tot4 + 255) / 256, 256>>>(in_proj_w, p_winh, p_winl, n, tot4);
        tot4 = DMODEL * DINNER / 4;
        split_hf4_kernel<<<(tot4 + 255) / 256, 256>>>(out_proj, p_woh, p_wol, tot4);
        split_hf4_kernel<<<(tot4 + 255) / 256, 256>>>(w2, p_w2h, p_w2l, tot4);
        w1eff_split_kernel<<<(1024 * 512 / 4 + 255) / 256, 256>>>(w1, p_w1h, p_w1l);
    }

    // 1) in_proj (bf16 3-pass)
    {
        dim3 grid(NPROJ_PAD / 128, BL / 128);
        hgemm3_kernel<0,0,0><<<grid, 256, GSM_BYTES>>>(p_xhi, p_xlo, p_winh, p_winl,
                                                       nullptr, p_zx, nullptr, nullptr,
                                                       BL, NPROJ, DMODEL);
    }
    // 2) conv + silu
    {
        size_t tot = (size_t)BL * (CONVD / 4);
        conv_silu_kernel<<<(unsigned)((tot + 255) / 256), 256>>>(p_zx, conv_w, conv_b, p_xc);
    }
    // 3) segmented selective scan
    scan_seg1_kernel<<<64 * SSEG, 256>>>(p_zx, p_xc, dt_bias, A_log, p_ys);
    scan_comb_kernel<<<64, 256>>>();
    scan_fix_kernel<<<64 * SSEG, 256>>>(p_xc, p_ys);
    // 4) gate + rmsnorm -> fp16 split
    gate_rms_kernel<<<BL, 256>>>(p_ys, p_xc, p_zx, Dv, rms_w, p_ybh, p_ybl);
    // 5) out_proj (fp16 2-pass)
    {
        dim3 grid(DMODEL / 128, BL / 128);
        hgemm3_kernel<0,0,1><<<grid, 256, GSM_BYTES>>>(p_ybh, p_ybl, p_woh, p_wol,
                                                       nullptr, p_y2, nullptr, nullptr,
                                                       BL, DMODEL, DINNER);
    }
    // 6) layernorm -> fp16 split
    layernorm_kernel<<<BL, 128>>>(p_y2, ln_g, ln_b, p_ylnh, p_ylnl);
    // 7) mlp hidden (fp16 2-pass, bias + silu, fp16-split out)
    {
        dim3 grid(DINNER / 128, BL / 128);
        hgemm3_kernel<2,1,1><<<grid, 256, GSM_BYTES>>>(p_ylnh, p_ylnl, p_w1h, p_w1l,
                                                       b1, nullptr, p_h1h, p_h1l,
                                                       BL, DINNER, DMODEL);
    }
    // 8) output (fp16 2-pass, bias)
    {
        dim3 grid(DMODEL / 128, BL / 128);
        hgemm3_kernel<1,0,1><<<grid, 256, GSM_BYTES>>>(p_h1h, p_h1l, p_w2h, p_w2l,
                                                       b2, outp, nullptr, nullptr,
                                                       BL, DMODEL, DINNER);
    }
}

// round 15
// speedup vs baseline: 1.1285x; 1.0215x over previous
#include <cuda_runtime.h>
#include <cuda_bf16.h>
#include <cuda_fp16.h>
#include <math.h>
#include <stdint.h>

// ---------------- problem constants ----------------
#define BB      4
#define LL      4096
#define DMODEL  512
#define DINNER  1024
#define DSTATE  64
#define HEADD   64
#define NHEADS  16
#define CONVD   1152
#define NPROJ   2192
#define NPROJ_PAD 2304      // 18*128
#define BL      (BB*LL)

// scan segmentation
#define SSEG    32
#define SEGL    (LL / SSEG)   // 128

// ---------------- scratch ----------------
__device__ float g_zx [(size_t)BL * NPROJ];
__device__ float g_xc [(size_t)BL * CONVD];
__device__ float g_ys [(size_t)BL * DINNER];
__device__ float g_y2 [(size_t)BL * DMODEL];
__device__ float g_hseg[64 * SSEG * 4096];
__device__ float g_hst [64 * SSEG * 4096];
__device__ float g_cum [64 * LL];

// pre-split operands: bf16 for in_proj, fp16 for the rest
__device__ __nv_bfloat16 g_xhi [(size_t)BL * DMODEL],  g_xlo [(size_t)BL * DMODEL];
__device__ __nv_bfloat16 g_winh[(size_t)NPROJ_PAD * DMODEL], g_winl[(size_t)NPROJ_PAD * DMODEL];
__device__ __half g_woh [DMODEL * DINNER], g_wol [DMODEL * DINNER];
__device__ __half g_w1h [DINNER * DMODEL], g_w1l [DINNER * DMODEL];
__device__ __half g_w2h [DMODEL * DINNER], g_w2l [DMODEL * DINNER];
__device__ __half g_ybh [(size_t)BL * DINNER], g_ybl [(size_t)BL * DINNER];
__device__ __half g_ylnh[(size_t)BL * DMODEL], g_ylnl[(size_t)BL * DMODEL];
__device__ __half g_h1h [(size_t)BL * DINNER], g_h1l [(size_t)BL * DINNER];

// ================= helpers =================
__device__ __forceinline__ unsigned pack16(unsigned short a, unsigned short b) {
    return (unsigned)a | ((unsigned)b << 16);
}
__device__ __forceinline__ void ldsm_x4(unsigned &r0, unsigned &r1,
                                        unsigned &r2, unsigned &r3, unsigned addr) {
    asm volatile("ldmatrix.sync.aligned.m8n8.x4.shared.b16 {%0,%1,%2,%3}, [%4];"
                 : "=r"(r0), "=r"(r1), "=r"(r2), "=r"(r3) : "r"(addr));
}
__device__ __forceinline__ void mma_bf(float* c, const unsigned* a, const unsigned* b) {
    asm volatile(
        "mma.sync.aligned.m16n8k16.row.col.f32.bf16.bf16.f32 "
        "{%0,%1,%2,%3}, {%4,%5,%6,%7}, {%8,%9}, {%0,%1,%2,%3};"
        : "+f"(c[0]), "+f"(c[1]), "+f"(c[2]), "+f"(c[3])
        : "r"(a[0]), "r"(a[1]), "r"(a[2]), "r"(a[3]), "r"(b[0]), "r"(b[1]));
}
__device__ __forceinline__ void mma_hf(float* c, const unsigned* a, const unsigned* b) {
    asm volatile(
        "mma.sync.aligned.m16n8k16.row.col.f32.f16.f16.f32 "
        "{%0,%1,%2,%3}, {%4,%5,%6,%7}, {%8,%9}, {%0,%1,%2,%3};"
        : "+f"(c[0]), "+f"(c[1]), "+f"(c[2]), "+f"(c[3])
        : "r"(a[0]), "r"(a[1]), "r"(a[2]), "r"(a[3]), "r"(b[0]), "r"(b[1]));
}
__device__ __forceinline__ void cp16(unsigned dst, const void* src) {
    asm volatile("cp.async.cg.shared.global [%0], [%1], 16;" :: "r"(dst), "l"(src));
}

#define TILE_BYTES   16384
#define BUF_BYTES    (2 * TILE_BYTES)
#define GSM_BYTES    (2 * BUF_BYTES)   // 64KB, 2-stage

// ================= GEMM: C = A @ W^T, pre-split hi/lo, 2-stage pipeline ==========
// H=0: bf16 3-pass (AhBh+AhBl+AlBh).  H=1: fp16 2-pass (AhBh+AlBh, no Bl).
template<int EPI, int OSPLIT, int H>
__global__ void __launch_bounds__(256, 2)
hgemm3_kernel(const void* __restrict__ Ahi_, const void* __restrict__ Alo_,
              const void* __restrict__ Whi_, const void* __restrict__ Wlo_,
              const float* __restrict__ bias, float* __restrict__ C,
              __half* __restrict__ Chi, __half* __restrict__ Clo,
              int M, int N, int K)
{
    const unsigned short* Ahi = (const unsigned short*)Ahi_;
    const unsigned short* Alo = (const unsigned short*)Alo_;
    const unsigned short* Whi = (const unsigned short*)Whi_;
    const unsigned short* Wlo = (const unsigned short*)Wlo_;

    extern __shared__ char smem[];

    const int tid  = threadIdx.x;
    const int lane = tid & 31;
    const int wid  = tid >> 5;
    const int wm   = wid & 1;
    const int wn   = wid >> 1;
    const int m0   = blockIdx.y * 128;
    const int n0   = blockIdx.x * 128;

    const int lrow = tid >> 1;
    const int half = tid & 1;
    const int rsw  = lrow & 7;
    const int c0 = 2 * half, c1 = 2 * half + 1, c2 = 4 + 2 * half, c3 = 5 + 2 * half;

    const unsigned s_u32 = (unsigned)__cvta_generic_to_shared(&smem[0]);
    const unsigned abase = s_u32 + (unsigned)(lrow * 128);
    const unsigned bbase = s_u32 + (unsigned)(TILE_BYTES + lrow * 128);

    unsigned aBase[4]; int aSw[4];
    const int kcA = lane >> 4;
#pragma unroll
    for (int mi = 0; mi < 4; mi++) {
        int r = wm * 64 + mi * 16 + (lane & 7) + ((lane >> 3) & 1) * 8;
        aBase[mi] = s_u32 + (unsigned)(r * 128);
        aSw[mi] = r & 7;
    }
    unsigned bBase[2]; int bSw[2];
    const int kcB = (lane >> 3) & 1;
#pragma unroll
    for (int pj = 0; pj < 2; pj++) {
        int r = wn * 32 + pj * 16 + ((lane >> 4) & 1) * 8 + (lane & 7);
        bBase[pj] = s_u32 + (unsigned)(TILE_BYTES + r * 128);
        bSw[pj] = r & 7;
    }

    float acc[4][4][4];
#pragma unroll
    for (int i = 0; i < 4; i++)
#pragma unroll
        for (int j = 0; j < 4; j++)
#pragma unroll
            for (int q = 0; q < 4; q++) acc[i][j][q] = 0.f;

    auto issue = [&](int k0, int buf) {
        unsigned bo = (unsigned)(buf * BUF_BYTES);
        const unsigned short* sa  = Ahi + (size_t)(m0 + lrow) * K + k0 + half * 16;
        const unsigned short* sal = Alo + (size_t)(m0 + lrow) * K + k0 + half * 16;
        const unsigned short* sb  = Whi + (size_t)(n0 + lrow) * K + k0 + half * 16;
        cp16(abase + bo + (unsigned)((c0 ^ rsw) * 16), sa);
        cp16(abase + bo + (unsigned)((c1 ^ rsw) * 16), sa + 8);
        cp16(abase + bo + (unsigned)((c2 ^ rsw) * 16), sal);
        cp16(abase + bo + (unsigned)((c3 ^ rsw) * 16), sal + 8);
        cp16(bbase + bo + (unsigned)((c0 ^ rsw) * 16), sb);
        cp16(bbase + bo + (unsigned)((c1 ^ rsw) * 16), sb + 8);
        if (!H) {
            const unsigned short* sbl = Wlo + (size_t)(n0 + lrow) * K + k0 + half * 16;
            cp16(bbase + bo + (unsigned)((c2 ^ rsw) * 16), sbl);
            cp16(bbase + bo + (unsigned)((c3 ^ rsw) * 16), sbl + 8);
        }
        asm volatile("cp.async.commit_group;" ::: "memory");
    };

    auto MMA = [&](float* c, const unsigned* a, const unsigned* b) {
        if (H) mma_hf(c, a, b); else mma_bf(c, a, b);
    };

    auto do_ks = [&](int ks, unsigned boff) {
        unsigned bh[4][2];
#pragma unroll
        for (int pj = 0; pj < 2; pj++) {
            unsigned r0, r1, r2, r3;
            ldsm_x4(r0, r1, r2, r3,
                    bBase[pj] + boff + (unsigned)((((ks * 2 + kcB)) ^ bSw[pj]) * 16));
            bh[pj * 2][0] = r0; bh[pj * 2][1] = r1;
            bh[pj * 2 + 1][0] = r2; bh[pj * 2 + 1][1] = r3;
        }
        if (!H) {
            unsigned bt[4][2];
#pragma unroll
            for (int pj = 0; pj < 2; pj++) {
                unsigned r0, r1, r2, r3;
                ldsm_x4(r0, r1, r2, r3,
                        bBase[pj] + boff + (unsigned)((((ks * 2 + kcB + 4)) ^ bSw[pj]) * 16));
                bt[pj * 2][0] = r0; bt[pj * 2][1] = r1;
                bt[pj * 2 + 1][0] = r2; bt[pj * 2 + 1][1] = r3;
            }
#pragma unroll
            for (int mi = 0; mi < 4; mi++) {
                unsigned a[4];
                ldsm_x4(a[0], a[1], a[2], a[3],
                        aBase[mi] + boff + (unsigned)((((ks * 2 + kcA)) ^ aSw[mi]) * 16));
#pragma unroll
                for (int nj = 0; nj < 4; nj++) MMA(acc[mi][nj], a, bh[nj]);
#pragma unroll
                for (int nj = 0; nj < 4; nj++) MMA(acc[mi][nj], a, bt[nj]);
                ldsm_x4(a[0], a[1], a[2], a[3],
                        aBase[mi] + boff + (unsigned)((((ks * 2 + kcA + 4)) ^ aSw[mi]) * 16));
#pragma unroll
                for (int nj = 0; nj < 4; nj++) MMA(acc[mi][nj], a, bh[nj]);
            }
        } else {
#pragma unroll
            for (int mi = 0; mi < 4; mi++) {
                unsigned a[4];
                ldsm_x4(a[0], a[1], a[2], a[3],
                        aBase[mi] + boff + (unsigned)((((ks * 2 + kcA)) ^ aSw[mi]) * 16));
#pragma unroll
                for (int nj = 0; nj < 4; nj++) MMA(acc[mi][nj], a, bh[nj]);
                ldsm_x4(a[0], a[1], a[2], a[3],
                        aBase[mi] + boff + (unsigned)((((ks * 2 + kcA + 4)) ^ aSw[mi]) * 16));
#pragma unroll
                for (int nj = 0; nj < 4; nj++) MMA(acc[mi][nj], a, bh[nj]);
            }
        }
    };

    issue(0, 0);
    const int nk = K >> 5;
    for (int it = 0; it < nk; it++) {
        asm volatile("cp.async.wait_group 0;" ::: "memory");
        __syncthreads();
        if (it + 1 < nk) issue((it + 1) * 32, (it + 1) & 1);
        const unsigned boff = (unsigned)((it & 1) * BUF_BYTES);
        do_ks(0, boff);
        do_ks(1, boff);
    }

    // epilogue
    const int row0 = m0 + wm * 64 + (lane >> 2);
    const int col0 = n0 + wn * 32 + (lane & 3) * 2;
#pragma unroll
    for (int mi = 0; mi < 4; mi++) {
#pragma unroll
        for (int nj = 0; nj < 4; nj++) {
            int col = col0 + nj * 8;
            if (col < N) {
                float b0 = 0.f, b1 = 0.f;
                if (EPI >= 1) { b0 = bias[col]; b1 = bias[col + 1]; }
                float v0 = acc[mi][nj][0] + b0;
                float v1 = acc[mi][nj][1] + b1;
                float v2 = acc[mi][nj][2] + b0;
                float v3 = acc[mi][nj][3] + b1;
                if (EPI == 2) {
                    v0 = v0 / (1.f + expf(-v0));
                    v1 = v1 / (1.f + expf(-v1));
                    v2 = v2 / (1.f + expf(-v2));
                    v3 = v3 / (1.f + expf(-v3));
                }
                int r = row0 + mi * 16;
                if (OSPLIT) {
                    __half h0 = __float2half(v0), h1 = __float2half(v1);
                    __half h2 = __float2half(v2), h3 = __float2half(v3);
                    __half l0 = __float2half(v0 - __half2float(h0));
                    __half l1 = __float2half(v1 - __half2float(h1));
                    __half l2 = __float2half(v2 - __half2float(h2));
                    __half l3 = __float2half(v3 - __half2float(h3));
                    *(unsigned*)&Chi[(size_t)r * N + col]       = pack16(*(unsigned short*)&h0, *(unsigned short*)&h1);
                    *(unsigned*)&Clo[(size_t)r * N + col]       = pack16(*(unsigned short*)&l0, *(unsigned short*)&l1);
                    *(unsigned*)&Chi[(size_t)(r + 8) * N + col] = pack16(*(unsigned short*)&h2, *(unsigned short*)&h3);
                    *(unsigned*)&Clo[(size_t)(r + 8) * N + col] = pack16(*(unsigned short*)&l2, *(unsigned short*)&l3);
                } else {
                    float2 p0; p0.x = v0; p0.y = v1;
                    float2 p1; p1.x = v2; p1.y = v3;
                    *(float2*)&C[(size_t)r * N + col] = p0;
                    *(float2*)&C[(size_t)(r + 8) * N + col] = p1;
                }
            }
        }
    }
}

// ---------------- vectorized splits (4 elems/thread) ----------------
__global__ void __launch_bounds__(256)
split_bf4_kernel(const float* __restrict__ src, __nv_bfloat16* __restrict__ hi,
                 __nv_bfloat16* __restrict__ lo, int n, int total4)
{
    int i4 = blockIdx.x * blockDim.x + threadIdx.x;
    if (i4 >= total4) return;
    int base = i4 * 4;
    float v[4];
#pragma unroll
    for (int j = 0; j < 4; j++) v[j] = (base + j < n) ? src[base + j] : 0.f;
    unsigned short h[4], l[4];
#pragma unroll
    for (int j = 0; j < 4; j++) {
        __nv_bfloat16 hb = __float2bfloat16(v[j]);
        __nv_bfloat16 lb = __float2bfloat16(v[j] - __bfloat162float(hb));
        h[j] = *(unsigned short*)&hb;
        l[j] = *(unsigned short*)&lb;
    }
    uint2 ho; ho.x = pack16(h[0], h[1]); ho.y = pack16(h[2], h[3]);
    uint2 lv; lv.x = pack16(l[0], l[1]); lv.y = pack16(l[2], l[3]);
    *(uint2*)&hi[base] = ho;
    *(uint2*)&lo[base] = lv;
}
__global__ void __launch_bounds__(256)
split_hf4_kernel(const float* __restrict__ src, __half* __restrict__ hi,
                 __half* __restrict__ lo, int total4)
{
    int i4 = blockIdx.x * blockDim.x + threadIdx.x;
    if (i4 >= total4) return;
    int base = i4 * 4;
    float4 v = *(const float4*)&src[base];
    float f[4] = {v.x, v.y, v.z, v.w};
    unsigned short h[4], l[4];
#pragma unroll
    for (int j = 0; j < 4; j++) {
        __half hb = __float2half(f[j]);
        __half lb = __float2half(f[j] - __half2float(hb));
        h[j] = *(unsigned short*)&hb;
        l[j] = *(unsigned short*)&lb;
    }
    uint2 ho; ho.x = pack16(h[0], h[1]); ho.y = pack16(h[2], h[3]);
    uint2 lv; lv.x = pack16(l[0], l[1]); lv.y = pack16(l[2], l[3]);
    *(uint2*)&hi[base] = ho;
    *(uint2*)&lo[base] = lv;
}
__global__ void __launch_bounds__(256)
w1eff_split_kernel(const float* __restrict__ w1, __half* __restrict__ hi,
                   __half* __restrict__ lo)
{
    int i4 = blockIdx.x * blockDim.x + threadIdx.x;
    if (i4 >= 1024 * 512 / 4) return;
    int base = i4 * 4;
    int n = base / 512, k = base % 512;
    float4 a = *(const float4*)&w1[n * 1024 + k];
    float4 b = *(const float4*)&w1[n * 1024 + 512 + k];
    float f[4] = {a.x + b.x, a.y + b.y, a.z + b.z, a.w + b.w};
    unsigned short h[4], l[4];
#pragma unroll
    for (int j = 0; j < 4; j++) {
        __half hb = __float2half(f[j]);
        __half lb = __float2half(f[j] - __half2float(hb));
        h[j] = *(unsigned short*)&hb;
        l[j] = *(unsigned short*)&lb;
    }
    uint2 ho; ho.x = pack16(h[0], h[1]); ho.y = pack16(h[2], h[3]);
    uint2 lv; lv.x = pack16(l[0], l[1]); lv.y = pack16(l[2], l[3]);
    *(uint2*)&hi[base] = ho;
    *(uint2*)&lo[base] = lv;
}

// ---------------- conv (anti-causal) + silu, float4 vectorized ----------------
__global__ void __launch_bounds__(256)
conv_silu_kernel(const float* __restrict__ zx, const float* __restrict__ cw,
                 const float* __restrict__ cb, float* __restrict__ xc)
{
    size_t idx = (size_t)blockIdx.x * blockDim.x + threadIdx.x;
    if (idx >= (size_t)BL * (CONVD / 4)) return;
    int c4 = (int)(idx % (CONVD / 4));
    int bl = (int)(idx / (CONVD / 4));
    int l  = bl % LL;
    int c  = c4 * 4;

    float4 acc = *(const float4*)&cb[c];
    float4 w0 = *(const float4*)&cw[c * 4 + 0];
    float4 w1 = *(const float4*)&cw[c * 4 + 4];
    float4 w2 = *(const float4*)&cw[c * 4 + 8];
    float4 w3 = *(const float4*)&cw[c * 4 + 12];

    const float* base = zx + (size_t)bl * NPROJ + DINNER + c;
#pragma unroll
    for (int k = 0; k < 4; k++) {
        int off = 3 - k;
        if (l + off < LL) {
            float4 v = *(const float4*)(base + (size_t)off * NPROJ);
            acc.x += ((const float*)&w0)[k] * v.x;
            acc.y += ((const float*)&w1)[k] * v.y;
            acc.z += ((const float*)&w2)[k] * v.z;
            acc.w += ((const float*)&w3)[k] * v.w;
        }
    }
    acc.x = acc.x / (1.f + expf(-acc.x));
    acc.y = acc.y / (1.f + expf(-acc.y));
    acc.z = acc.z / (1.f + expf(-acc.z));
    acc.w = acc.w / (1.f + expf(-acc.w));
    *(float4*)&xc[(size_t)bl * CONVD + c] = acc;
}

// ---------------- scan pass 1 (occupancy-capped: 4 CTAs/SM) ----------------
__global__ void __launch_bounds__(256, 4)
scan_seg1_kernel(const float* __restrict__ zx, const float* __restrict__ xc,
                 const float* __restrict__ dt_bias, const float* __restrict__ A_log,
                 float* __restrict__ yout)
{
    int blk = blockIdx.x;
    int seg = blk & (SSEG - 1);
    int bh  = blk / SSEG;
    int b = bh >> 4, h = bh & 15;
    int tid = threadIdx.x;
    int pl = tid >> 2;
    int ng = tid & 3;

    float Acoef = -expf(A_log[h]);
    float dtb   = dt_bias[h];

    __shared__ float sB[2][8][64], sC[2][8][64], sX[2][8][64];
    __shared__ float sdt[2][8], sDA[2][8];

    float hs[16];
#pragma unroll
    for (int j = 0; j < 16; j++) hs[j] = 0.f;

    float rBC[4], rX[2], rDR = 0.f;
    const int sBeg = seg * SEGL;
    const int sEnd = sBeg + SEGL;

    float runP = 1.f;

    auto preload = [&](int s0) {
#pragma unroll
        for (int i = 0; i < 4; i++) {
            int e = tid + i * 256;
            int t = e >> 7, q = e & 127;
            int bl = b * LL + (LL - 1 - (s0 + t));
            rBC[i] = xc[(size_t)bl * CONVD + DINNER + q];
        }
#pragma unroll
        for (int i = 0; i < 2; i++) {
            int e = tid + i * 256;
            int t = e >> 6, j = e & 63;
            int bl = b * LL + (LL - 1 - (s0 + t));
            rX[i] = xc[(size_t)bl * CONVD + h * HEADD + j];
        }
        if (tid < 8) {
            int bl = b * LL + (LL - 1 - (s0 + tid));
            rDR = zx[(size_t)bl * NPROJ + (2 * DINNER + 2 * DSTATE) + h];
        }
    };
    auto commit_smem = [&](int buf) {
#pragma unroll
        for (int i = 0; i < 4; i++) {
            int e = tid + i * 256;
            int t = e >> 7, q = e & 127;
            if (q < 64) sB[buf][t][q] = rBC[i]; else sC[buf][t][q - 64] = rBC[i];
        }
#pragma unroll
        for (int i = 0; i < 2; i++) {
            int e = tid + i * 256;
            int t = e >> 6, j = e & 63;
            sX[buf][t][j] = rX[i];
        }
        if (tid < 8) {
            float dr = rDR + dtb;
            float dt = (dr > 20.f) ? dr : log1pf(expf(dr));
            sdt[buf][tid] = dt;
            sDA[buf][tid] = expf(dt * Acoef);
        }
    };

    preload(sBeg);
    commit_smem(0);
    __syncthreads();

    for (int s0 = sBeg; s0 < sEnd; s0 += 8) {
        int buf = ((s0 - sBeg) >> 3) & 1;
        bool more = (s0 + 8) < sEnd;
        if (more) preload(s0 + 8);

        if (tid == 0) {
            float* cw = &g_cum[(size_t)bh * LL + s0];
#pragma unroll
            for (int t = 0; t < 8; t++) { runP *= sDA[buf][t]; cw[t] = runP; }
        }

        float yv[8];
#pragma unroll
        for (int t = 0; t < 8; t++) {
            float dA  = sDA[buf][t];
            float dtx = sdt[buf][t] * sX[buf][t][pl];
            float yp = 0.f;
#pragma unroll
            for (int u = 0; u < 4; u++) {
                float4 bb = *(const float4*)&sB[buf][t][u * 16 + ng * 4];
                hs[u*4+0] = hs[u*4+0] * dA + dtx * bb.x;
                hs[u*4+1] = hs[u*4+1] * dA + dtx * bb.y;
                hs[u*4+2] = hs[u*4+2] * dA + dtx * bb.z;
                hs[u*4+3] = hs[u*4+3] * dA + dtx * bb.w;
            }
#pragma unroll
            for (int u = 0; u < 4; u++) {
                float4 cc = *(const float4*)&sC[buf][t][u * 16 + ng * 4];
                yp += hs[u*4+0] * cc.x + hs[u*4+1] * cc.y
                    + hs[u*4+2] * cc.z + hs[u*4+3] * cc.w;
            }
            yv[t] = yp;
        }
#pragma unroll
        for (int t = 0; t < 8; t++) yv[t] += __shfl_xor_sync(0xffffffffu, yv[t], 1);
#pragma unroll
        for (int t = 0; t < 8; t++) yv[t] += __shfl_xor_sync(0xffffffffu, yv[t], 2);
        if (ng == 0) {
#pragma unroll
            for (int t = 0; t < 8; t++) {
                int l = LL - 1 - (s0 + t);
                yout[((size_t)(b * LL + l)) * DINNER + h * HEADD + pl] = yv[t];
            }
        }

        if (more) commit_smem(buf ^ 1);
        __syncthreads();
    }

    {
        float* hd = &g_hseg[((size_t)blk) * 4096 + pl * 64];
#pragma unroll
        for (int j = 0; j < 16; j++) {
            int n = ((j >> 2) << 4) + (ng << 2) + (j & 3);
            hd[n] = hs[j];
        }
    }
}

// ---------------- scan pass 2 ----------------
__global__ void __launch_bounds__(256)
scan_comb_kernel()
{
    int bh = blockIdx.x;
    int tid = threadIdx.x;
    float hst[16];
#pragma unroll
    for (int i = 0; i < 16; i++) hst[i] = 0.f;

    for (int seg = 0; seg < SSEG; seg++) {
        float P = g_cum[(size_t)bh * LL + seg * SEGL + SEGL - 1];
#pragma unroll
        for (int i = 0; i < 16; i++) {
            int e = tid + i * 256;
            size_t base = ((size_t)(bh * SSEG + seg)) * 4096 + e;
            g_hst[base] = hst[i];
            hst[i] = P * hst[i] + g_hseg[base];
        }
    }
}

// ---------------- scan pass 3 (occupancy-capped: 4 CTAs/SM) ----------------
__global__ void __launch_bounds__(256, 4)
scan_fix_kernel(const float* __restrict__ xc, float* __restrict__ yout)
{
    int blk = blockIdx.x;
    int seg = blk & (SSEG - 1);
    if (seg == 0) return;
    int bh  = blk / SSEG;
    int b = bh >> 4, h = bh & 15;
    int tid = threadIdx.x;
    int pl = tid >> 2;
    int ng = tid & 3;

    float hs[16];
    {
        const float* hp = &g_hst[((size_t)blk) * 4096 + pl * 64];
#pragma unroll
        for (int j = 0; j < 16; j++) {
            int n = ((j >> 2) << 4) + (ng << 2) + (j & 3);
            hs[j] = hp[n];
        }
    }

    __shared__ float sC[8][64];
    __shared__ float sCum[8];
    const int sBeg = seg * SEGL;

    for (int s0 = sBeg; s0 < sBeg + SEGL; s0 += 8) {
#pragma unroll
        for (int i = 0; i < 2; i++) {
            int e = tid + i * 256;
            int t = e >> 6, q = e & 63;
            int bl = b * LL + (LL - 1 - (s0 + t));
            sC[t][q] = xc[(size_t)bl * CONVD + DINNER + DSTATE + q];
        }
        if (tid < 8) sCum[tid] = g_cum[(size_t)bh * LL + s0 + tid];
        __syncthreads();

        float yv[8];
#pragma unroll
        for (int t = 0; t < 8; t++) {
            float yp0 = 0.f, yp1 = 0.f, yp2 = 0.f, yp3 = 0.f;
#pragma unroll
            for (int u = 0; u < 4; u++) {
                float4 cc = *(const float4*)&sC[t][u * 16 + ng * 4];
                yp0 += hs[u*4+0] * cc.x;
                yp1 += hs[u*4+1] * cc.y;
                yp2 += hs[u*4+2] * cc.z;
                yp3 += hs[u*4+3] * cc.w;
            }
            yv[t] = ((yp0 + yp1) + (yp2 + yp3)) * sCum[t];
        }
#pragma unroll
        for (int t = 0; t < 8; t++) yv[t] += __shfl_xor_sync(0xffffffffu, yv[t], 1);
#pragma unroll
        for (int t = 0; t < 8; t++) yv[t] += __shfl_xor_sync(0xffffffffu, yv[t], 2);
        if (ng == 0) {
#pragma unroll
            for (int t = 0; t < 8; t++) {
                int l = LL - 1 - (s0 + t);
                size_t idx = ((size_t)(b * LL + l)) * DINNER + h * HEADD + pl;
                yout[idx] += yv[t];
            }
        }
        __syncthreads();
    }
}

// ---------------- block reduction helper ----------------
__device__ __forceinline__ float block_reduce_sum(float v) {
    __shared__ float sred[32];
    int lane = threadIdx.x & 31, w = threadIdx.x >> 5;
#pragma unroll
    for (int o = 16; o; o >>= 1) v += __shfl_xor_sync(0xffffffffu, v, o);
    if (lane == 0) sred[w] = v;
    __syncthreads();
    int nw = blockDim.x >> 5;
    float r = (threadIdx.x < nw) ? sred[threadIdx.x] : 0.f;
    if (w == 0) {
#pragma unroll
        for (int o = 16; o; o >>= 1) r += __shfl_xor_sync(0xffffffffu, r, o);
        if (lane == 0) sred[0] = r;
    }
    __syncthreads();
    float out = sred[0];
    __syncthreads();
    return out;
}

// ---------------- gate + rmsnorm -> split fp16 (vectorized) ----------------
__global__ void __launch_bounds__(256)
gate_rms_kernel(const float* __restrict__ ys, const float* __restrict__ xc,
                const float* __restrict__ zx, const float* __restrict__ Dv,
                const float* __restrict__ rw,
                __half* __restrict__ ybh, __half* __restrict__ ybl)
{
    int row = blockIdx.x;
    int c = threadIdx.x * 4;
    size_t oy = (size_t)row * DINNER, oc = (size_t)row * CONVD, oz = (size_t)row * NPROJ;
    float4 yv = *(const float4*)&ys[oy + c];
    float4 xv = *(const float4*)&xc[oc + c];
    float4 zv = *(const float4*)&zx[oz + c];
    float Dh = Dv[c >> 6];
    float v[4];
    {
        float z[4] = {zv.x, zv.y, zv.z, zv.w};
        float yy[4] = {yv.x, yv.y, yv.z, yv.w};
        float xx[4] = {xv.x, xv.y, xv.z, xv.w};
#pragma unroll
        for (int j = 0; j < 4; j++) {
            float sz = z[j] / (1.f + expf(-z[j]));
            v[j] = (yy[j] + Dh * xx[j]) * sz;
        }
    }
    float ss = v[0]*v[0] + v[1]*v[1] + v[2]*v[2] + v[3]*v[3];
    ss = block_reduce_sum(ss);
    float r = rsqrtf(ss * (1.f / (float)DINNER) + 1e-5f);
    float4 rwv = *(const float4*)&rw[c];
    float rr[4] = {rwv.x, rwv.y, rwv.z, rwv.w};
    unsigned short h[4], l[4];
#pragma unroll
    for (int j = 0; j < 4; j++) {
        float val = v[j] * r * rr[j];
        __half hh = __float2half(val);
        __half ll = __float2half(val - __half2float(hh));
        h[j] = *(unsigned short*)&hh;
        l[j] = *(unsigned short*)&ll;
    }
    uint2 ho; ho.x = pack16(h[0], h[1]); ho.y = pack16(h[2], h[3]);
    uint2 lo; lo.x = pack16(l[0], l[1]); lo.y = pack16(l[2], l[3]);
    *(uint2*)&ybh[oy + c] = ho;
    *(uint2*)&ybl[oy + c] = lo;
}

// ---------------- layernorm -> split fp16 (vectorized) ----------------
__global__ void __launch_bounds__(128)
layernorm_kernel(const float* __restrict__ x, const float* __restrict__ g,
                 const float* __restrict__ bpar,
                 __half* __restrict__ oh, __half* __restrict__ ol)
{
    int row = blockIdx.x;
    int c = threadIdx.x * 4;
    size_t o = (size_t)row * DMODEL;
    float4 xv = *(const float4*)&x[o + c];
    float v[4] = {xv.x, xv.y, xv.z, xv.w};
    float s = v[0] + v[1] + v[2] + v[3];
    s = block_reduce_sum(s);
    float m = s * (1.f / (float)DMODEL);
    float ss = 0.f;
#pragma unroll
    for (int j = 0; j < 4; j++) { float d = v[j] - m; ss += d * d; }
    ss = block_reduce_sum(ss);
    float r = rsqrtf(ss * (1.f / (float)DMODEL) + 1e-5f);
    float4 gv = *(const float4*)&g[c];
    float4 bv = *(const float4*)&bpar[c];
    float gg[4] = {gv.x, gv.y, gv.z, gv.w};
    float bb[4] = {bv.x, bv.y, bv.z, bv.w};
    unsigned short h[4], l[4];
#pragma unroll
    for (int j = 0; j < 4; j++) {
        float val = (v[j] - m) * r * gg[j] + bb[j];
        __half hh = __float2half(val);
        __half ll = __float2half(val - __half2float(hh));
        h[j] = *(unsigned short*)&hh;
        l[j] = *(unsigned short*)&ll;
    }
    uint2 ho; ho.x = pack16(h[0], h[1]); ho.y = pack16(h[2], h[3]);
    uint2 lo; lo.x = pack16(l[0], l[1]); lo.y = pack16(l[2], l[3]);
    *(uint2*)&oh[o + c] = ho;
    *(uint2*)&ol[o + c] = lo;
}

// ---------------- launch ----------------
extern "C" void kernel_launch(void* const* d_in, const int* in_sizes, int n_in,
                              void* d_out, int out_size)
{
    const float* x         = (const float*)d_in[0];
    const float* in_proj_w = (const float*)d_in[1];
    const float* conv_w    = (const float*)d_in[2];
    const float* conv_b    = (const float*)d_in[3];
    const float* dt_bias   = (const float*)d_in[4];
    const float* A_log     = (const float*)d_in[5];
    const float* Dv        = (const float*)d_in[6];
    const float* rms_w     = (const float*)d_in[7];
    const float* out_proj  = (const float*)d_in[8];
    const float* ln_g      = (const float*)d_in[9];
    const float* ln_b      = (const float*)d_in[10];
    const float* w1        = (const float*)d_in[11];
    const float* b1        = (const float*)d_in[12];
    const float* w2        = (const float*)d_in[13];
    const float* b2        = (const float*)d_in[14];
    float* outp            = (float*)d_out;

    float *p_zx, *p_xc, *p_ys, *p_y2;
    cudaGetSymbolAddress((void**)&p_zx,  g_zx);
    cudaGetSymbolAddress((void**)&p_xc,  g_xc);
    cudaGetSymbolAddress((void**)&p_ys,  g_ys);
    cudaGetSymbolAddress((void**)&p_y2,  g_y2);

    __nv_bfloat16 *p_xhi, *p_xlo, *p_winh, *p_winl;
    __half *p_woh, *p_wol, *p_w1h, *p_w1l, *p_w2h, *p_w2l;
    __half *p_ybh, *p_ybl, *p_ylnh, *p_ylnl, *p_h1h, *p_h1l;
    cudaGetSymbolAddress((void**)&p_xhi,  g_xhi);
    cudaGetSymbolAddress((void**)&p_xlo,  g_xlo);
    cudaGetSymbolAddress((void**)&p_winh, g_winh);
    cudaGetSymbolAddress((void**)&p_winl, g_winl);
    cudaGetSymbolAddress((void**)&p_woh,  g_woh);
    cudaGetSymbolAddress((void**)&p_wol,  g_wol);
    cudaGetSymbolAddress((void**)&p_w1h,  g_w1h);
    cudaGetSymbolAddress((void**)&p_w1l,  g_w1l);
    cudaGetSymbolAddress((void**)&p_w2h,  g_w2h);
    cudaGetSymbolAddress((void**)&p_w2l,  g_w2l);
    cudaGetSymbolAddress((void**)&p_ybh,  g_ybh);
    cudaGetSymbolAddress((void**)&p_ybl,  g_ybl);
    cudaGetSymbolAddress((void**)&p_ylnh, g_ylnh);
    cudaGetSymbolAddress((void**)&p_ylnl, g_ylnl);
    cudaGetSymbolAddress((void**)&p_h1h,  g_h1h);
    cudaGetSymbolAddress((void**)&p_h1l,  g_h1l);

    static bool attr_done = false;
    if (!attr_done) {
        cudaFuncSetAttribute(hgemm3_kernel<0,0,0>, cudaFuncAttributeMaxDynamicSharedMemorySize, GSM_BYTES);
        cudaFuncSetAttribute(hgemm3_kernel<0,0,1>, cudaFuncAttributeMaxDynamicSharedMemorySize, GSM_BYTES);
        cudaFuncSetAttribute(hgemm3_kernel<1,0,1>, cudaFuncAttributeMaxDynamicSharedMemorySize, GSM_BYTES);
        cudaFuncSetAttribute(hgemm3_kernel<2,1,1>, cudaFuncAttributeMaxDynamicSharedMemorySize, GSM_BYTES);
        attr_done = true;
    }

    // operand splitting (vectorized)
    {
        int n, tot4;
        n = BL * DMODEL; tot4 = n / 4;
        split_bf4_kernel<<<(tot4 + 255) / 256, 256>>>(x, p_xhi, p_xlo, n, tot4);
        n = NPROJ * DMODEL; tot4 = NPROJ_PAD * DMODEL / 4;
        split_bf4_kernel<<<(tot4 + 255) / 256, 256>>>(in_proj_w, p_winh, p_winl, n, tot4);
        tot4 = DMODEL * DINNER / 4;
        split_hf4_kernel<<<(tot4 + 255) / 256, 256>>>(out_proj, p_woh, p_wol, tot4);
        split_hf4_kernel<<<(tot4 + 255) / 256, 256>>>(w2, p_w2h, p_w2l, tot4);
        w1eff_split_kernel<<<(1024 * 512 / 4 + 255) / 256, 256>>>(w1, p_w1h, p_w1l);
    }

    // 1) in_proj (bf16 3-pass)
    {
        dim3 grid(NPROJ_PAD / 128, BL / 128);
        hgemm3_kernel<0,0,0><<<grid, 256, GSM_BYTES>>>(p_xhi, p_xlo, p_winh, p_winl,
                                                       nullptr, p_zx, nullptr, nullptr,
                                                       BL, NPROJ, DMODEL);
    }
    // 2) conv + silu
    {
        size_t tot = (size_t)BL * (CONVD / 4);
        conv_silu_kernel<<<(unsigned)((tot + 255) / 256), 256>>>(p_zx, conv_w, conv_b, p_xc);
    }
    // 3) segmented selective scan
    scan_seg1_kernel<<<64 * SSEG, 256>>>(p_zx, p_xc, dt_bias, A_log, p_ys);
    scan_comb_kernel<<<64, 256>>>();
    scan_fix_kernel<<<64 * SSEG, 256>>>(p_xc, p_ys);
    // 4) gate + rmsnorm -> fp16 split
    gate_rms_kernel<<<BL, 256>>>(p_ys, p_xc, p_zx, Dv, rms_w, p_ybh, p_ybl);
    // 5) out_proj (fp16 2-pass)
    {
        dim3 grid(DMODEL / 128, BL / 128);
        hgemm3_kernel<0,0,1><<<grid, 256, GSM_BYTES>>>(p_ybh, p_ybl, p_woh, p_wol,
                                                       nullptr, p_y2, nullptr, nullptr,
                                                       BL, DMODEL, DINNER);
    }
    // 6) layernorm -> fp16 split
    layernorm_kernel<<<BL, 128>>>(p_y2, ln_g, ln_b, p_ylnh, p_ylnl);
    // 7) mlp hidden (fp16 2-pass, bias + silu, fp16-split out)
    {
        dim3 grid(DINNER / 128, BL / 128);
        hgemm3_kernel<2,1,1><<<grid, 256, GSM_BYTES>>>(p_ylnh, p_ylnl, p_w1h, p_w1l,
                                                       b1, nullptr, p_h1h, p_h1l,
                                                       BL, DINNER, DMODEL);
    }
    // 8) output (fp16 2-pass, bias)
    {
        dim3 grid(DMODEL / 128, BL / 128);
        hgemm3_kernel<1,0,1><<<grid, 256, GSM_BYTES>>>(p_h1h, p_h1l, p_w2h, p_w2l,
                                                       b2, outp, nullptr, nullptr,
                                                       BL, DMODEL, DINNER);
    }
}

// round 16
// speedup vs baseline: 1.2478x; 1.1057x over previous
#include <cuda_runtime.h>
#include <cuda_bf16.h>
#include <cuda_fp16.h>
#include <math.h>
#include <stdint.h>

// ---------------- problem constants ----------------
#define BB      4
#define LL      4096
#define DMODEL  512
#define DINNER  1024
#define DSTATE  64
#define HEADD   64
#define NHEADS  16
#define CONVD   1152
#define NPROJ   2192
#define NPROJ_PAD 2304      // 18*128
#define BL      (BB*LL)

// scan segmentation
#define SSEG    32
#define SEGL    (LL / SSEG)   // 128

// ---------------- scratch ----------------
__device__ float g_zx [(size_t)BL * NPROJ];
__device__ float g_xc [(size_t)BL * CONVD];
__device__ float g_ys [(size_t)BL * DINNER];
__device__ float g_y2 [(size_t)BL * DMODEL];
__device__ float g_hseg[64 * SSEG * 4096];
__device__ float g_hst [64 * SSEG * 4096];
__device__ float g_cum [64 * LL];

// pre-split fp16 operands (all GEMMs fp16; in_proj mixed 2/3-pass)
__device__ __half g_xhi [(size_t)BL * DMODEL],  g_xlo [(size_t)BL * DMODEL];
__device__ __half g_winh[(size_t)NPROJ_PAD * DMODEL], g_winl[(size_t)NPROJ_PAD * DMODEL];
__device__ __half g_woh [DMODEL * DINNER], g_wol [DMODEL * DINNER];
__device__ __half g_w1h [DINNER * DMODEL], g_w1l [DINNER * DMODEL];
__device__ __half g_w2h [DMODEL * DINNER], g_w2l [DMODEL * DINNER];
__device__ __half g_ybh [(size_t)BL * DINNER], g_ybl [(size_t)BL * DINNER];
__device__ __half g_ylnh[(size_t)BL * DMODEL], g_ylnl[(size_t)BL * DMODEL];
__device__ __half g_h1h [(size_t)BL * DINNER], g_h1l [(size_t)BL * DINNER];

// ================= helpers =================
__device__ __forceinline__ unsigned pack16(unsigned short a, unsigned short b) {
    return (unsigned)a | ((unsigned)b << 16);
}
__device__ __forceinline__ void ldsm_x4(unsigned &r0, unsigned &r1,
                                        unsigned &r2, unsigned &r3, unsigned addr) {
    asm volatile("ldmatrix.sync.aligned.m8n8.x4.shared.b16 {%0,%1,%2,%3}, [%4];"
                 : "=r"(r0), "=r"(r1), "=r"(r2), "=r"(r3) : "r"(addr));
}
__device__ __forceinline__ void mma_hf(float* c, const unsigned* a, const unsigned* b) {
    asm volatile(
        "mma.sync.aligned.m16n8k16.row.col.f32.f16.f16.f32 "
        "{%0,%1,%2,%3}, {%4,%5,%6,%7}, {%8,%9}, {%0,%1,%2,%3};"
        : "+f"(c[0]), "+f"(c[1]), "+f"(c[2]), "+f"(c[3])
        : "r"(a[0]), "r"(a[1]), "r"(a[2]), "r"(a[3]), "r"(b[0]), "r"(b[1]));
}
__device__ __forceinline__ void cp16(unsigned dst, const void* src) {
    asm volatile("cp.async.cg.shared.global [%0], [%1], 16;" :: "r"(dst), "l"(src));
}

#define TILE_BYTES   16384
#define BUF_BYTES    (2 * TILE_BYTES)
#define GSM_BYTES    (2 * BUF_BYTES)   // 64KB, 2-stage

// ================= GEMM: C = A @ W^T, fp16 split hi/lo, 2-stage pipeline =========
// Per-CTA pass count: tiles with n0 >= n3_start run 3-pass (AhBh+AlBh+AhBl),
// others 2-pass (AhBh+AlBh). Pass n3_start=N to make everything 2-pass.
// EPI: 0 none, 1 +bias, 2 +bias+silu.  OSPLIT: 1 -> fp16 hi/lo out.
template<int EPI, int OSPLIT>
__global__ void __launch_bounds__(256, 2)
hgemm2_kernel(const __half* __restrict__ Ahi_, const __half* __restrict__ Alo_,
              const __half* __restrict__ Whi_, const __half* __restrict__ Wlo_,
              const float* __restrict__ bias, float* __restrict__ C,
              __half* __restrict__ Chi, __half* __restrict__ Clo,
              int M, int N, int K, int n3_start)
{
    const unsigned short* Ahi = (const unsigned short*)Ahi_;
    const unsigned short* Alo = (const unsigned short*)Alo_;
    const unsigned short* Whi = (const unsigned short*)Whi_;
    const unsigned short* Wlo = (const unsigned short*)Wlo_;

    extern __shared__ char smem[];

    const int tid  = threadIdx.x;
    const int lane = tid & 31;
    const int wid  = tid >> 5;
    const int wm   = wid & 1;
    const int wn   = wid >> 1;
    const int m0   = blockIdx.y * 128;
    const int n0   = blockIdx.x * 128;
    const bool three = (n0 >= n3_start);

    const int lrow = tid >> 1;
    const int half = tid & 1;
    const int rsw  = lrow & 7;
    const int c0 = 2 * half, c1 = 2 * half + 1, c2 = 4 + 2 * half, c3 = 5 + 2 * half;

    const unsigned s_u32 = (unsigned)__cvta_generic_to_shared(&smem[0]);
    const unsigned abase = s_u32 + (unsigned)(lrow * 128);
    const unsigned bbase = s_u32 + (unsigned)(TILE_BYTES + lrow * 128);

    unsigned aBase[4]; int aSw[4];
    const int kcA = lane >> 4;
#pragma unroll
    for (int mi = 0; mi < 4; mi++) {
        int r = wm * 64 + mi * 16 + (lane & 7) + ((lane >> 3) & 1) * 8;
        aBase[mi] = s_u32 + (unsigned)(r * 128);
        aSw[mi] = r & 7;
    }
    unsigned bBase[2]; int bSw[2];
    const int kcB = (lane >> 3) & 1;
#pragma unroll
    for (int pj = 0; pj < 2; pj++) {
        int r = wn * 32 + pj * 16 + ((lane >> 4) & 1) * 8 + (lane & 7);
        bBase[pj] = s_u32 + (unsigned)(TILE_BYTES + r * 128);
        bSw[pj] = r & 7;
    }

    float acc[4][4][4];
#pragma unroll
    for (int i = 0; i < 4; i++)
#pragma unroll
        for (int j = 0; j < 4; j++)
#pragma unroll
            for (int q = 0; q < 4; q++) acc[i][j][q] = 0.f;

    auto issue = [&](int k0, int buf) {
        unsigned bo = (unsigned)(buf * BUF_BYTES);
        const unsigned short* sa  = Ahi + (size_t)(m0 + lrow) * K + k0 + half * 16;
        const unsigned short* sal = Alo + (size_t)(m0 + lrow) * K + k0 + half * 16;
        const unsigned short* sb  = Whi + (size_t)(n0 + lrow) * K + k0 + half * 16;
        cp16(abase + bo + (unsigned)((c0 ^ rsw) * 16), sa);
        cp16(abase + bo + (unsigned)((c1 ^ rsw) * 16), sa + 8);
        cp16(abase + bo + (unsigned)((c2 ^ rsw) * 16), sal);
        cp16(abase + bo + (unsigned)((c3 ^ rsw) * 16), sal + 8);
        cp16(bbase + bo + (unsigned)((c0 ^ rsw) * 16), sb);
        cp16(bbase + bo + (unsigned)((c1 ^ rsw) * 16), sb + 8);
        if (three) {
            const unsigned short* sbl = Wlo + (size_t)(n0 + lrow) * K + k0 + half * 16;
            cp16(bbase + bo + (unsigned)((c2 ^ rsw) * 16), sbl);
            cp16(bbase + bo + (unsigned)((c3 ^ rsw) * 16), sbl + 8);
        }
        asm volatile("cp.async.commit_group;" ::: "memory");
    };

    auto do_ks = [&](int ks, unsigned boff) {
        unsigned bh[4][2];
#pragma unroll
        for (int pj = 0; pj < 2; pj++) {
            unsigned r0, r1, r2, r3;
            ldsm_x4(r0, r1, r2, r3,
                    bBase[pj] + boff + (unsigned)((((ks * 2 + kcB)) ^ bSw[pj]) * 16));
            bh[pj * 2][0] = r0; bh[pj * 2][1] = r1;
            bh[pj * 2 + 1][0] = r2; bh[pj * 2 + 1][1] = r3;
        }
        if (three) {
            unsigned bt[4][2];
#pragma unroll
            for (int pj = 0; pj < 2; pj++) {
                unsigned r0, r1, r2, r3;
                ldsm_x4(r0, r1, r2, r3,
                        bBase[pj] + boff + (unsigned)((((ks * 2 + kcB + 4)) ^ bSw[pj]) * 16));
                bt[pj * 2][0] = r0; bt[pj * 2][1] = r1;
                bt[pj * 2 + 1][0] = r2; bt[pj * 2 + 1][1] = r3;
            }
#pragma unroll
            for (int mi = 0; mi < 4; mi++) {
                unsigned a[4];
                ldsm_x4(a[0], a[1], a[2], a[3],
                        aBase[mi] + boff + (unsigned)((((ks * 2 + kcA)) ^ aSw[mi]) * 16));
#pragma unroll
                for (int nj = 0; nj < 4; nj++) mma_hf(acc[mi][nj], a, bh[nj]);
#pragma unroll
                for (int nj = 0; nj < 4; nj++) mma_hf(acc[mi][nj], a, bt[nj]);
                ldsm_x4(a[0], a[1], a[2], a[3],
                        aBase[mi] + boff + (unsigned)((((ks * 2 + kcA + 4)) ^ aSw[mi]) * 16));
#pragma unroll
                for (int nj = 0; nj < 4; nj++) mma_hf(acc[mi][nj], a, bh[nj]);
            }
        } else {
#pragma unroll
            for (int mi = 0; mi < 4; mi++) {
                unsigned a[4];
                ldsm_x4(a[0], a[1], a[2], a[3],
                        aBase[mi] + boff + (unsigned)((((ks * 2 + kcA)) ^ aSw[mi]) * 16));
#pragma unroll
                for (int nj = 0; nj < 4; nj++) mma_hf(acc[mi][nj], a, bh[nj]);
                ldsm_x4(a[0], a[1], a[2], a[3],
                        aBase[mi] + boff + (unsigned)((((ks * 2 + kcA + 4)) ^ aSw[mi]) * 16));
#pragma unroll
                for (int nj = 0; nj < 4; nj++) mma_hf(acc[mi][nj], a, bh[nj]);
            }
        }
    };

    issue(0, 0);
    const int nk = K >> 5;
    for (int it = 0; it < nk; it++) {
        asm volatile("cp.async.wait_group 0;" ::: "memory");
        __syncthreads();
        if (it + 1 < nk) issue((it + 1) * 32, (it + 1) & 1);
        const unsigned boff = (unsigned)((it & 1) * BUF_BYTES);
        do_ks(0, boff);
        do_ks(1, boff);
    }

    // epilogue
    const int row0 = m0 + wm * 64 + (lane >> 2);
    const int col0 = n0 + wn * 32 + (lane & 3) * 2;
#pragma unroll
    for (int mi = 0; mi < 4; mi++) {
#pragma unroll
        for (int nj = 0; nj < 4; nj++) {
            int col = col0 + nj * 8;
            if (col < N) {
                float b0 = 0.f, b1 = 0.f;
                if (EPI >= 1) { b0 = bias[col]; b1 = bias[col + 1]; }
                float v0 = acc[mi][nj][0] + b0;
                float v1 = acc[mi][nj][1] + b1;
                float v2 = acc[mi][nj][2] + b0;
                float v3 = acc[mi][nj][3] + b1;
                if (EPI == 2) {
                    v0 = v0 / (1.f + expf(-v0));
                    v1 = v1 / (1.f + expf(-v1));
                    v2 = v2 / (1.f + expf(-v2));
                    v3 = v3 / (1.f + expf(-v3));
                }
                int r = row0 + mi * 16;
                if (OSPLIT) {
                    __half h0 = __float2half(v0), h1 = __float2half(v1);
                    __half h2 = __float2half(v2), h3 = __float2half(v3);
                    __half l0 = __float2half(v0 - __half2float(h0));
                    __half l1 = __float2half(v1 - __half2float(h1));
                    __half l2 = __float2half(v2 - __half2float(h2));
                    __half l3 = __float2half(v3 - __half2float(h3));
                    *(unsigned*)&Chi[(size_t)r * N + col]       = pack16(*(unsigned short*)&h0, *(unsigned short*)&h1);
                    *(unsigned*)&Clo[(size_t)r * N + col]       = pack16(*(unsigned short*)&l0, *(unsigned short*)&l1);
                    *(unsigned*)&Chi[(size_t)(r + 8) * N + col] = pack16(*(unsigned short*)&h2, *(unsigned short*)&h3);
                    *(unsigned*)&Clo[(size_t)(r + 8) * N + col] = pack16(*(unsigned short*)&l2, *(unsigned short*)&l3);
                } else {
                    float2 p0; p0.x = v0; p0.y = v1;
                    float2 p1; p1.x = v2; p1.y = v3;
                    *(float2*)&C[(size_t)r * N + col] = p0;
                    *(float2*)&C[(size_t)(r + 8) * N + col] = p1;
                }
            }
        }
    }
}

// ---------------- vectorized splits ----------------
__global__ void __launch_bounds__(256)
split_hf4_kernel(const float* __restrict__ src, __half* __restrict__ hi,
                 __half* __restrict__ lo, int total4)
{
    int i4 = blockIdx.x * blockDim.x + threadIdx.x;
    if (i4 >= total4) return;
    int base = i4 * 4;
    float4 v = *(const float4*)&src[base];
    float f[4] = {v.x, v.y, v.z, v.w};
    unsigned short h[4], l[4];
#pragma unroll
    for (int j = 0; j < 4; j++) {
        __half hb = __float2half(f[j]);
        __half lb = __float2half(f[j] - __half2float(hb));
        h[j] = *(unsigned short*)&hb;
        l[j] = *(unsigned short*)&lb;
    }
    uint2 ho; ho.x = pack16(h[0], h[1]); ho.y = pack16(h[2], h[3]);
    uint2 lv; lv.x = pack16(l[0], l[1]); lv.y = pack16(l[2], l[3]);
    *(uint2*)&hi[base] = ho;
    *(uint2*)&lo[base] = lv;
}
// padded variant (zero-fills beyond n)
__global__ void __launch_bounds__(256)
split_hf4p_kernel(const float* __restrict__ src, __half* __restrict__ hi,
                  __half* __restrict__ lo, int n, int total4)
{
    int i4 = blockIdx.x * blockDim.x + threadIdx.x;
    if (i4 >= total4) return;
    int base = i4 * 4;
    float f[4];
#pragma unroll
    for (int j = 0; j < 4; j++) f[j] = (base + j < n) ? src[base + j] : 0.f;
    unsigned short h[4], l[4];
#pragma unroll
    for (int j = 0; j < 4; j++) {
        __half hb = __float2half(f[j]);
        __half lb = __float2half(f[j] - __half2float(hb));
        h[j] = *(unsigned short*)&hb;
        l[j] = *(unsigned short*)&lb;
    }
    uint2 ho; ho.x = pack16(h[0], h[1]); ho.y = pack16(h[2], h[3]);
    uint2 lv; lv.x = pack16(l[0], l[1]); lv.y = pack16(l[2], l[3]);
    *(uint2*)&hi[base] = ho;
    *(uint2*)&lo[base] = lv;
}
__global__ void __launch_bounds__(256)
w1eff_split_kernel(const float* __restrict__ w1, __half* __restrict__ hi,
                   __half* __restrict__ lo)
{
    int i4 = blockIdx.x * blockDim.x + threadIdx.x;
    if (i4 >= 1024 * 512 / 4) return;
    int base = i4 * 4;
    int n = base / 512, k = base % 512;
    float4 a = *(const float4*)&w1[n * 1024 + k];
    float4 b = *(const float4*)&w1[n * 1024 + 512 + k];
    float f[4] = {a.x + b.x, a.y + b.y, a.z + b.z, a.w + b.w};
    unsigned short h[4], l[4];
#pragma unroll
    for (int j = 0; j < 4; j++) {
        __half hb = __float2half(f[j]);
        __half lb = __float2half(f[j] - __half2float(hb));
        h[j] = *(unsigned short*)&hb;
        l[j] = *(unsigned short*)&lb;
    }
    uint2 ho; ho.x = pack16(h[0], h[1]); ho.y = pack16(h[2], h[3]);
    uint2 lv; lv.x = pack16(l[0], l[1]); lv.y = pack16(l[2], l[3]);
    *(uint2*)&hi[base] = ho;
    *(uint2*)&lo[base] = lv;
}

// ---------------- conv (anti-causal) + silu, float4 vectorized ----------------
__global__ void __launch_bounds__(256)
conv_silu_kernel(const float* __restrict__ zx, const float* __restrict__ cw,
                 const float* __restrict__ cb, float* __restrict__ xc)
{
    size_t idx = (size_t)blockIdx.x * blockDim.x + threadIdx.x;
    if (idx >= (size_t)BL * (CONVD / 4)) return;
    int c4 = (int)(idx % (CONVD / 4));
    int bl = (int)(idx / (CONVD / 4));
    int l  = bl % LL;
    int c  = c4 * 4;

    float4 acc = *(const float4*)&cb[c];
    float4 w0 = *(const float4*)&cw[c * 4 + 0];
    float4 w1 = *(const float4*)&cw[c * 4 + 4];
    float4 w2 = *(const float4*)&cw[c * 4 + 8];
    float4 w3 = *(const float4*)&cw[c * 4 + 12];

    const float* base = zx + (size_t)bl * NPROJ + DINNER + c;
#pragma unroll
    for (int k = 0; k < 4; k++) {
        int off = 3 - k;
        if (l + off < LL) {
            float4 v = *(const float4*)(base + (size_t)off * NPROJ);
            acc.x += ((const float*)&w0)[k] * v.x;
            acc.y += ((const float*)&w1)[k] * v.y;
            acc.z += ((const float*)&w2)[k] * v.z;
            acc.w += ((const float*)&w3)[k] * v.w;
        }
    }
    acc.x = acc.x / (1.f + expf(-acc.x));
    acc.y = acc.y / (1.f + expf(-acc.y));
    acc.z = acc.z / (1.f + expf(-acc.z));
    acc.w = acc.w / (1.f + expf(-acc.w));
    *(float4*)&xc[(size_t)bl * CONVD + c] = acc;
}

// ---------------- scan pass 1 (occupancy-capped: 4 CTAs/SM) ----------------
__global__ void __launch_bounds__(256, 4)
scan_seg1_kernel(const float* __restrict__ zx, const float* __restrict__ xc,
                 const float* __restrict__ dt_bias, const float* __restrict__ A_log,
                 float* __restrict__ yout)
{
    int blk = blockIdx.x;
    int seg = blk & (SSEG - 1);
    int bh  = blk / SSEG;
    int b = bh >> 4, h = bh & 15;
    int tid = threadIdx.x;
    int pl = tid >> 2;
    int ng = tid & 3;

    float Acoef = -expf(A_log[h]);
    float dtb   = dt_bias[h];

    __shared__ float sB[2][8][64], sC[2][8][64], sX[2][8][64];
    __shared__ float sdt[2][8], sDA[2][8];

    float hs[16];
#pragma unroll
    for (int j = 0; j < 16; j++) hs[j] = 0.f;

    float rBC[4], rX[2], rDR = 0.f;
    const int sBeg = seg * SEGL;
    const int sEnd = sBeg + SEGL;

    float runP = 1.f;

    auto preload = [&](int s0) {
#pragma unroll
        for (int i = 0; i < 4; i++) {
            int e = tid + i * 256;
            int t = e >> 7, q = e & 127;
            int bl = b * LL + (LL - 1 - (s0 + t));
            rBC[i] = xc[(size_t)bl * CONVD + DINNER + q];
        }
#pragma unroll
        for (int i = 0; i < 2; i++) {
            int e = tid + i * 256;
            int t = e >> 6, j = e & 63;
            int bl = b * LL + (LL - 1 - (s0 + t));
            rX[i] = xc[(size_t)bl * CONVD + h * HEADD + j];
        }
        if (tid < 8) {
            int bl = b * LL + (LL - 1 - (s0 + tid));
            rDR = zx[(size_t)bl * NPROJ + (2 * DINNER + 2 * DSTATE) + h];
        }
    };
    auto commit_smem = [&](int buf) {
#pragma unroll
        for (int i = 0; i < 4; i++) {
            int e = tid + i * 256;
            int t = e >> 7, q = e & 127;
            if (q < 64) sB[buf][t][q] = rBC[i]; else sC[buf][t][q - 64] = rBC[i];
        }
#pragma unroll
        for (int i = 0; i < 2; i++) {
            int e = tid + i * 256;
            int t = e >> 6, j = e & 63;
            sX[buf][t][j] = rX[i];
        }
        if (tid < 8) {
            float dr = rDR + dtb;
            float dt = (dr > 20.f) ? dr : log1pf(expf(dr));
            sdt[buf][tid] = dt;
            sDA[buf][tid] = expf(dt * Acoef);
        }
    };

    preload(sBeg);
    commit_smem(0);
    __syncthreads();

    for (int s0 = sBeg; s0 < sEnd; s0 += 8) {
        int buf = ((s0 - sBeg) >> 3) & 1;
        bool more = (s0 + 8) < sEnd;
        if (more) preload(s0 + 8);

        if (tid == 0) {
            float* cw = &g_cum[(size_t)bh * LL + s0];
#pragma unroll
            for (int t = 0; t < 8; t++) { runP *= sDA[buf][t]; cw[t] = runP; }
        }

        float yv[8];
#pragma unroll
        for (int t = 0; t < 8; t++) {
            float dA  = sDA[buf][t];
            float dtx = sdt[buf][t] * sX[buf][t][pl];
            float yp = 0.f;
#pragma unroll
            for (int u = 0; u < 4; u++) {
                float4 bb = *(const float4*)&sB[buf][t][u * 16 + ng * 4];
                hs[u*4+0] = hs[u*4+0] * dA + dtx * bb.x;
                hs[u*4+1] = hs[u*4+1] * dA + dtx * bb.y;
                hs[u*4+2] = hs[u*4+2] * dA + dtx * bb.z;
                hs[u*4+3] = hs[u*4+3] * dA + dtx * bb.w;
            }
#pragma unroll
            for (int u = 0; u < 4; u++) {
                float4 cc = *(const float4*)&sC[buf][t][u * 16 + ng * 4];
                yp += hs[u*4+0] * cc.x + hs[u*4+1] * cc.y
                    + hs[u*4+2] * cc.z + hs[u*4+3] * cc.w;
            }
            yv[t] = yp;
        }
#pragma unroll
        for (int t = 0; t < 8; t++) yv[t] += __shfl_xor_sync(0xffffffffu, yv[t], 1);
#pragma unroll
        for (int t = 0; t < 8; t++) yv[t] += __shfl_xor_sync(0xffffffffu, yv[t], 2);
        if (ng == 0) {
#pragma unroll
            for (int t = 0; t < 8; t++) {
                int l = LL - 1 - (s0 + t);
                yout[((size_t)(b * LL + l)) * DINNER + h * HEADD + pl] = yv[t];
            }
        }

        if (more) commit_smem(buf ^ 1);
        __syncthreads();
    }

    {
        float* hd = &g_hseg[((size_t)blk) * 4096 + pl * 64];
#pragma unroll
        for (int j = 0; j < 16; j++) {
            int n = ((j >> 2) << 4) + (ng << 2) + (j & 3);
            hd[n] = hs[j];
        }
    }
}

// ---------------- scan pass 2 (parallelized: 512 blocks, float2/thread) --------
__global__ void __launch_bounds__(256)
scan_comb_kernel()
{
    int bh = blockIdx.x >> 3;
    int ch = blockIdx.x & 7;
    int e0 = ch * 512 + threadIdx.x * 2;
    float h0 = 0.f, h1 = 0.f;

    for (int seg = 0; seg < SSEG; seg++) {
        float P = g_cum[(size_t)bh * LL + seg * SEGL + SEGL - 1];
        size_t base = ((size_t)(bh * SSEG + seg)) * 4096 + e0;
        float2 hv = *(const float2*)&g_hseg[base];
        float2 st; st.x = h0; st.y = h1;
        *(float2*)&g_hst[base] = st;
        h0 = P * h0 + hv.x;
        h1 = P * h1 + hv.y;
    }
}

// ---------------- scan pass 3 (occupancy-capped: 4 CTAs/SM) ----------------
__global__ void __launch_bounds__(256, 4)
scan_fix_kernel(const float* __restrict__ xc, float* __restrict__ yout)
{
    int blk = blockIdx.x;
    int seg = blk & (SSEG - 1);
    if (seg == 0) return;
    int bh  = blk / SSEG;
    int b = bh >> 4, h = bh & 15;
    int tid = threadIdx.x;
    int pl = tid >> 2;
    int ng = tid & 3;

    float hs[16];
    {
        const float* hp = &g_hst[((size_t)blk) * 4096 + pl * 64];
#pragma unroll
        for (int j = 0; j < 16; j++) {
            int n = ((j >> 2) << 4) + (ng << 2) + (j & 3);
            hs[j] = hp[n];
        }
    }

    __shared__ float sC[8][64];
    __shared__ float sCum[8];
    const int sBeg = seg * SEGL;

    for (int s0 = sBeg; s0 < sBeg + SEGL; s0 += 8) {
#pragma unroll
        for (int i = 0; i < 2; i++) {
            int e = tid + i * 256;
            int t = e >> 6, q = e & 63;
            int bl = b * LL + (LL - 1 - (s0 + t));
            sC[t][q] = xc[(size_t)bl * CONVD + DINNER + DSTATE + q];
        }
        if (tid < 8) sCum[tid] = g_cum[(size_t)bh * LL + s0 + tid];
        __syncthreads();

        float yv[8];
#pragma unroll
        for (int t = 0; t < 8; t++) {
            float yp0 = 0.f, yp1 = 0.f, yp2 = 0.f, yp3 = 0.f;
#pragma unroll
            for (int u = 0; u < 4; u++) {
                float4 cc = *(const float4*)&sC[t][u * 16 + ng * 4];
                yp0 += hs[u*4+0] * cc.x;
                yp1 += hs[u*4+1] * cc.y;
                yp2 += hs[u*4+2] * cc.z;
                yp3 += hs[u*4+3] * cc.w;
            }
            yv[t] = ((yp0 + yp1) + (yp2 + yp3)) * sCum[t];
        }
#pragma unroll
        for (int t = 0; t < 8; t++) yv[t] += __shfl_xor_sync(0xffffffffu, yv[t], 1);
#pragma unroll
        for (int t = 0; t < 8; t++) yv[t] += __shfl_xor_sync(0xffffffffu, yv[t], 2);
        if (ng == 0) {
#pragma unroll
            for (int t = 0; t < 8; t++) {
                int l = LL - 1 - (s0 + t);
                size_t idx = ((size_t)(b * LL + l)) * DINNER + h * HEADD + pl;
                yout[idx] += yv[t];
            }
        }
        __syncthreads();
    }
}

// ---------------- block reduction helper ----------------
__device__ __forceinline__ float block_reduce_sum(float v) {
    __shared__ float sred[32];
    int lane = threadIdx.x & 31, w = threadIdx.x >> 5;
#pragma unroll
    for (int o = 16; o; o >>= 1) v += __shfl_xor_sync(0xffffffffu, v, o);
    if (lane == 0) sred[w] = v;
    __syncthreads();
    int nw = blockDim.x >> 5;
    float r = (threadIdx.x < nw) ? sred[threadIdx.x] : 0.f;
    if (w == 0) {
#pragma unroll
        for (int o = 16; o; o >>= 1) r += __shfl_xor_sync(0xffffffffu, r, o);
        if (lane == 0) sred[0] = r;
    }
    __syncthreads();
    float out = sred[0];
    __syncthreads();
    return out;
}

// ---------------- gate + rmsnorm -> split fp16 (vectorized) ----------------
__global__ void __launch_bounds__(256)
gate_rms_kernel(const float* __restrict__ ys, const float* __restrict__ xc,
                const float* __restrict__ zx, const float* __restrict__ Dv,
                const float* __restrict__ rw,
                __half* __restrict__ ybh, __half* __restrict__ ybl)
{
    int row = blockIdx.x;
    int c = threadIdx.x * 4;
    size_t oy = (size_t)row * DINNER, oc = (size_t)row * CONVD, oz = (size_t)row * NPROJ;
    float4 yv = *(const float4*)&ys[oy + c];
    float4 xv = *(const float4*)&xc[oc + c];
    float4 zv = *(const float4*)&zx[oz + c];
    float Dh = Dv[c >> 6];
    float v[4];
    {
        float z[4] = {zv.x, zv.y, zv.z, zv.w};
        float yy[4] = {yv.x, yv.y, yv.z, yv.w};
        float xx[4] = {xv.x, xv.y, xv.z, xv.w};
#pragma unroll
        for (int j = 0; j < 4; j++) {
            float sz = z[j] / (1.f + expf(-z[j]));
            v[j] = (yy[j] + Dh * xx[j]) * sz;
        }
    }
    float ss = v[0]*v[0] + v[1]*v[1] + v[2]*v[2] + v[3]*v[3];
    ss = block_reduce_sum(ss);
    float r = rsqrtf(ss * (1.f / (float)DINNER) + 1e-5f);
    float4 rwv = *(const float4*)&rw[c];
    float rr[4] = {rwv.x, rwv.y, rwv.z, rwv.w};
    unsigned short h[4], l[4];
#pragma unroll
    for (int j = 0; j < 4; j++) {
        float val = v[j] * r * rr[j];
        __half hh = __float2half(val);
        __half ll = __float2half(val - __half2float(hh));
        h[j] = *(unsigned short*)&hh;
        l[j] = *(unsigned short*)&ll;
    }
    uint2 ho; ho.x = pack16(h[0], h[1]); ho.y = pack16(h[2], h[3]);
    uint2 lo; lo.x = pack16(l[0], l[1]); lo.y = pack16(l[2], l[3]);
    *(uint2*)&ybh[oy + c] = ho;
    *(uint2*)&ybl[oy + c] = lo;
}

// ---------------- layernorm -> split fp16 (vectorized) ----------------
__global__ void __launch_bounds__(128)
layernorm_kernel(const float* __restrict__ x, const float* __restrict__ g,
                 const float* __restrict__ bpar,
                 __half* __restrict__ oh, __half* __restrict__ ol)
{
    int row = blockIdx.x;
    int c = threadIdx.x * 4;
    size_t o = (size_t)row * DMODEL;
    float4 xv = *(const float4*)&x[o + c];
    float v[4] = {xv.x, xv.y, xv.z, xv.w};
    float s = v[0] + v[1] + v[2] + v[3];
    s = block_reduce_sum(s);
    float m = s * (1.f / (float)DMODEL);
    float ss = 0.f;
#pragma unroll
    for (int j = 0; j < 4; j++) { float d = v[j] - m; ss += d * d; }
    ss = block_reduce_sum(ss);
    float r = rsqrtf(ss * (1.f / (float)DMODEL) + 1e-5f);
    float4 gv = *(const float4*)&g[c];
    float4 bv = *(const float4*)&bpar[c];
    float gg[4] = {gv.x, gv.y, gv.z, gv.w};
    float bb[4] = {bv.x, bv.y, bv.z, bv.w};
    unsigned short h[4], l[4];
#pragma unroll
    for (int j = 0; j < 4; j++) {
        float val = (v[j] - m) * r * gg[j] + bb[j];
        __half hh = __float2half(val);
        __half ll = __float2half(val - __half2float(hh));
        h[j] = *(unsigned short*)&hh;
        l[j] = *(unsigned short*)&ll;
    }
    uint2 ho; ho.x = pack16(h[0], h[1]); ho.y = pack16(h[2], h[3]);
    uint2 lo; lo.x = pack16(l[0], l[1]); lo.y = pack16(l[2], l[3]);
    *(uint2*)&oh[o + c] = ho;
    *(uint2*)&ol[o + c] = lo;
}

// ---------------- launch ----------------
extern "C" void kernel_launch(void* const* d_in, const int* in_sizes, int n_in,
                              void* d_out, int out_size)
{
    const float* x         = (const float*)d_in[0];
    const float* in_proj_w = (const float*)d_in[1];
    const float* conv_w    = (const float*)d_in[2];
    const float* conv_b    = (const float*)d_in[3];
    const float* dt_bias   = (const float*)d_in[4];
    const float* A_log     = (const float*)d_in[5];
    const float* Dv        = (const float*)d_in[6];
    const float* rms_w     = (const float*)d_in[7];
    const float* out_proj  = (const float*)d_in[8];
    const float* ln_g      = (const float*)d_in[9];
    const float* ln_b      = (const float*)d_in[10];
    const float* w1        = (const float*)d_in[11];
    const float* b1        = (const float*)d_in[12];
    const float* w2        = (const float*)d_in[13];
    const float* b2        = (const float*)d_in[14];
    float* outp            = (float*)d_out;

    float *p_zx, *p_xc, *p_ys, *p_y2;
    cudaGetSymbolAddress((void**)&p_zx,  g_zx);
    cudaGetSymbolAddress((void**)&p_xc,  g_xc);
    cudaGetSymbolAddress((void**)&p_ys,  g_ys);
    cudaGetSymbolAddress((void**)&p_y2,  g_y2);

    __half *p_xhi, *p_xlo, *p_winh, *p_winl;
    __half *p_woh, *p_wol, *p_w1h, *p_w1l, *p_w2h, *p_w2l;
    __half *p_ybh, *p_ybl, *p_ylnh, *p_ylnl, *p_h1h, *p_h1l;
    cudaGetSymbolAddress((void**)&p_xhi,  g_xhi);
    cudaGetSymbolAddress((void**)&p_xlo,  g_xlo);
    cudaGetSymbolAddress((void**)&p_winh, g_winh);
    cudaGetSymbolAddress((void**)&p_winl, g_winl);
    cudaGetSymbolAddress((void**)&p_woh,  g_woh);
    cudaGetSymbolAddress((void**)&p_wol,  g_wol);
    cudaGetSymbolAddress((void**)&p_w1h,  g_w1h);
    cudaGetSymbolAddress((void**)&p_w1l,  g_w1l);
    cudaGetSymbolAddress((void**)&p_w2h,  g_w2h);
    cudaGetSymbolAddress((void**)&p_w2l,  g_w2l);
    cudaGetSymbolAddress((void**)&p_ybh,  g_ybh);
    cudaGetSymbolAddress((void**)&p_ybl,  g_ybl);
    cudaGetSymbolAddress((void**)&p_ylnh, g_ylnh);
    cudaGetSymbolAddress((void**)&p_ylnl, g_ylnl);
    cudaGetSymbolAddress((void**)&p_h1h,  g_h1h);
    cudaGetSymbolAddress((void**)&p_h1l,  g_h1l);

    static bool attr_done = false;
    if (!attr_done) {
        cudaFuncSetAttribute(hgemm2_kernel<0,0>, cudaFuncAttributeMaxDynamicSharedMemorySize, GSM_BYTES);
        cudaFuncSetAttribute(hgemm2_kernel<1,0>, cudaFuncAttributeMaxDynamicSharedMemorySize, GSM_BYTES);
        cudaFuncSetAttribute(hgemm2_kernel<2,1>, cudaFuncAttributeMaxDynamicSharedMemorySize, GSM_BYTES);
        attr_done = true;
    }

    // operand splitting (vectorized, all fp16)
    {
        int n, tot4;
        tot4 = BL * DMODEL / 4;
        split_hf4_kernel<<<(tot4 + 255) / 256, 256>>>(x, p_xhi, p_xlo, tot4);
        n = NPROJ * DMODEL; tot4 = NPROJ_PAD * DMODEL / 4;
        split_hf4p_kernel<<<(tot4 + 255) / 256, 256>>>(in_proj_w, p_winh, p_winl, n, tot4);
        tot4 = DMODEL * DINNER / 4;
        split_hf4_kernel<<<(tot4 + 255) / 256, 256>>>(out_proj, p_woh, p_wol, tot4);
        split_hf4_kernel<<<(tot4 + 255) / 256, 256>>>(w2, p_w2h, p_w2l, tot4);
        w1eff_split_kernel<<<(1024 * 512 / 4 + 255) / 256, 256>>>(w1, p_w1h, p_w1l);
    }

    // 1) in_proj (fp16; 2-pass except dt tile n0>=2176 which is 3-pass)
    {
        dim3 grid(NPROJ_PAD / 128, BL / 128);
        hgemm2_kernel<0,0><<<grid, 256, GSM_BYTES>>>(p_xhi, p_xlo, p_winh, p_winl,
                                                     nullptr, p_zx, nullptr, nullptr,
                                                     BL, NPROJ, DMODEL, 2176);
    }
    // 2) conv + silu
    {
        size_t tot = (size_t)BL * (CONVD / 4);
        conv_silu_kernel<<<(unsigned)((tot + 255) / 256), 256>>>(p_zx, conv_w, conv_b, p_xc);
    }
    // 3) segmented selective scan
    scan_seg1_kernel<<<64 * SSEG, 256>>>(p_zx, p_xc, dt_bias, A_log, p_ys);
    scan_comb_kernel<<<64 * 8, 256>>>();
    scan_fix_kernel<<<64 * SSEG, 256>>>(p_xc, p_ys);
    // 4) gate + rmsnorm -> fp16 split
    gate_rms_kernel<<<BL, 256>>>(p_ys, p_xc, p_zx, Dv, rms_w, p_ybh, p_ybl);
    // 5) out_proj (fp16 2-pass)
    {
        dim3 grid(DMODEL / 128, BL / 128);
        hgemm2_kernel<0,0><<<grid, 256, GSM_BYTES>>>(p_ybh, p_ybl, p_woh, nullptr,
                                                     nullptr, p_y2, nullptr, nullptr,
                                                     BL, DMODEL, DINNER, DMODEL);
    }
    // 6) layernorm -> fp16 split
    layernorm_kernel<<<BL, 128>>>(p_y2, ln_g, ln_b, p_ylnh, p_ylnl);
    // 7) mlp hidden (fp16 2-pass, bias + silu, fp16-split out)
    {
        dim3 grid(DINNER / 128, BL / 128);
        hgemm2_kernel<2,1><<<grid, 256, GSM_BYTES>>>(p_ylnh, p_ylnl, p_w1h, nullptr,
                                                     b1, nullptr, p_h1h, p_h1l,
                                                     BL, DINNER, DMODEL, DINNER);
    }
    // 8) output (fp16 2-pass, bias)
    {
        dim3 grid(DMODEL / 128, BL / 128);
        hgemm2_kernel<1,0><<<grid, 256, GSM_BYTES>>>(p_h1h, p_h1l, p_w2h, nullptr,
                                                     b2, outp, nullptr, nullptr,
                                                     BL, DMODEL, DINNER, DMODEL);
    }
}

// round 17
// speedup vs baseline: 1.2769x; 1.0234x over previous
#include <cuda_runtime.h>
#include <cuda_bf16.h>
#include <cuda_fp16.h>
#include <math.h>
#include <stdint.h>

// ---------------- problem constants ----------------
#define BB      4
#define LL      4096
#define DMODEL  512
#define DINNER  1024
#define DSTATE  64
#define HEADD   64
#define NHEADS  16
#define CONVD   1152
#define NPROJ   2192
#define NPROJ_PAD 2304      // 18*128
#define BL      (BB*LL)

// scan segmentation
#define SSEG    32
#define SEGL    (LL / SSEG)   // 128

// ---------------- scratch ----------------
__device__ float g_zx [(size_t)BL * NPROJ];
__device__ float g_xc [(size_t)BL * CONVD];
__device__ float g_ys [(size_t)BL * DINNER];
__device__ float g_y2 [(size_t)BL * DMODEL];
__device__ float g_hseg[64 * SSEG * 4096];
__device__ float g_hst [64 * SSEG * 4096];
__device__ float g_cum [64 * LL];

// pre-split fp16 operands
__device__ __half g_xhi [(size_t)BL * DMODEL],  g_xlo [(size_t)BL * DMODEL];
__device__ __half g_winh[(size_t)NPROJ_PAD * DMODEL], g_winl[(size_t)NPROJ_PAD * DMODEL];
__device__ __half g_woh [DMODEL * DINNER], g_wol [DMODEL * DINNER];
__device__ __half g_w1h [DINNER * DMODEL], g_w1l [DINNER * DMODEL];
__device__ __half g_w2h [DMODEL * DINNER], g_w2l [DMODEL * DINNER];
__device__ __half g_ybh [(size_t)BL * DINNER], g_ybl [(size_t)BL * DINNER];
__device__ __half g_ylnh[(size_t)BL * DMODEL], g_ylnl[(size_t)BL * DMODEL];
__device__ __half g_h1h [(size_t)BL * DINNER], g_h1l [(size_t)BL * DINNER];

// ================= helpers =================
__device__ __forceinline__ unsigned pack16(unsigned short a, unsigned short b) {
    return (unsigned)a | ((unsigned)b << 16);
}
__device__ __forceinline__ void ldsm_x4(unsigned &r0, unsigned &r1,
                                        unsigned &r2, unsigned &r3, unsigned addr) {
    asm volatile("ldmatrix.sync.aligned.m8n8.x4.shared.b16 {%0,%1,%2,%3}, [%4];"
                 : "=r"(r0), "=r"(r1), "=r"(r2), "=r"(r3) : "r"(addr));
}
__device__ __forceinline__ void mma_hf(float* c, const unsigned* a, const unsigned* b) {
    asm volatile(
        "mma.sync.aligned.m16n8k16.row.col.f32.f16.f16.f32 "
        "{%0,%1,%2,%3}, {%4,%5,%6,%7}, {%8,%9}, {%0,%1,%2,%3};"
        : "+f"(c[0]), "+f"(c[1]), "+f"(c[2]), "+f"(c[3])
        : "r"(a[0]), "r"(a[1]), "r"(a[2]), "r"(a[3]), "r"(b[0]), "r"(b[1]));
}
__device__ __forceinline__ void cp16(unsigned dst, const void* src) {
    asm volatile("cp.async.cg.shared.global [%0], [%1], 16;" :: "r"(dst), "l"(src));
}

#define TILE_BYTES   16384
#define BUF_BYTES    (2 * TILE_BYTES)
#define GSM_BYTES    (2 * BUF_BYTES)   // 64KB, 2-stage

// ================= GEMM: C = A @ W^T, fp16 split hi/lo, 2-stage pipeline =========
// NP = number of A passes (1: AhBh only; 2: AhBh+AlBh).
// Tiles with n0 >= n3_start additionally run the AhBl pass (3-pass; NP must be 2).
// EPI: 0 none, 1 +bias, 2 +bias+silu.
// OSPLIT: 0 -> fp32 C, 1 -> fp16 hi+lo out, 2 -> fp16 hi-only out.
template<int EPI, int OSPLIT, int NP>
__global__ void __launch_bounds__(256, 2)
hgemm2_kernel(const __half* __restrict__ Ahi_, const __half* __restrict__ Alo_,
              const __half* __restrict__ Whi_, const __half* __restrict__ Wlo_,
              const float* __restrict__ bias, float* __restrict__ C,
              __half* __restrict__ Chi, __half* __restrict__ Clo,
              int M, int N, int K, int n3_start)
{
    const unsigned short* Ahi = (const unsigned short*)Ahi_;
    const unsigned short* Alo = (const unsigned short*)Alo_;
    const unsigned short* Whi = (const unsigned short*)Whi_;
    const unsigned short* Wlo = (const unsigned short*)Wlo_;

    extern __shared__ char smem[];

    const int tid  = threadIdx.x;
    const int lane = tid & 31;
    const int wid  = tid >> 5;
    const int wm   = wid & 1;
    const int wn   = wid >> 1;
    const int m0   = blockIdx.y * 128;
    const int n0   = blockIdx.x * 128;
    const bool three = (n0 >= n3_start);

    const int lrow = tid >> 1;
    const int half = tid & 1;
    const int rsw  = lrow & 7;
    const int c0 = 2 * half, c1 = 2 * half + 1, c2 = 4 + 2 * half, c3 = 5 + 2 * half;

    const unsigned s_u32 = (unsigned)__cvta_generic_to_shared(&smem[0]);
    const unsigned abase = s_u32 + (unsigned)(lrow * 128);
    const unsigned bbase = s_u32 + (unsigned)(TILE_BYTES + lrow * 128);

    unsigned aBase[4]; int aSw[4];
    const int kcA = lane >> 4;
#pragma unroll
    for (int mi = 0; mi < 4; mi++) {
        int r = wm * 64 + mi * 16 + (lane & 7) + ((lane >> 3) & 1) * 8;
        aBase[mi] = s_u32 + (unsigned)(r * 128);
        aSw[mi] = r & 7;
    }
    unsigned bBase[2]; int bSw[2];
    const int kcB = (lane >> 3) & 1;
#pragma unroll
    for (int pj = 0; pj < 2; pj++) {
        int r = wn * 32 + pj * 16 + ((lane >> 4) & 1) * 8 + (lane & 7);
        bBase[pj] = s_u32 + (unsigned)(TILE_BYTES + r * 128);
        bSw[pj] = r & 7;
    }

    float acc[4][4][4];
#pragma unroll
    for (int i = 0; i < 4; i++)
#pragma unroll
        for (int j = 0; j < 4; j++)
#pragma unroll
            for (int q = 0; q < 4; q++) acc[i][j][q] = 0.f;

    auto issue = [&](int k0, int buf) {
        unsigned bo = (unsigned)(buf * BUF_BYTES);
        const unsigned short* sa  = Ahi + (size_t)(m0 + lrow) * K + k0 + half * 16;
        const unsigned short* sb  = Whi + (size_t)(n0 + lrow) * K + k0 + half * 16;
        cp16(abase + bo + (unsigned)((c0 ^ rsw) * 16), sa);
        cp16(abase + bo + (unsigned)((c1 ^ rsw) * 16), sa + 8);
        if (NP == 2 || three) {
            const unsigned short* sal = Alo + (size_t)(m0 + lrow) * K + k0 + half * 16;
            cp16(abase + bo + (unsigned)((c2 ^ rsw) * 16), sal);
            cp16(abase + bo + (unsigned)((c3 ^ rsw) * 16), sal + 8);
        }
        cp16(bbase + bo + (unsigned)((c0 ^ rsw) * 16), sb);
        cp16(bbase + bo + (unsigned)((c1 ^ rsw) * 16), sb + 8);
        if (three) {
            const unsigned short* sbl = Wlo + (size_t)(n0 + lrow) * K + k0 + half * 16;
            cp16(bbase + bo + (unsigned)((c2 ^ rsw) * 16), sbl);
            cp16(bbase + bo + (unsigned)((c3 ^ rsw) * 16), sbl + 8);
        }
        asm volatile("cp.async.commit_group;" ::: "memory");
    };

    auto do_ks = [&](int ks, unsigned boff) {
        unsigned bh[4][2];
#pragma unroll
        for (int pj = 0; pj < 2; pj++) {
            unsigned r0, r1, r2, r3;
            ldsm_x4(r0, r1, r2, r3,
                    bBase[pj] + boff + (unsigned)((((ks * 2 + kcB)) ^ bSw[pj]) * 16));
            bh[pj * 2][0] = r0; bh[pj * 2][1] = r1;
            bh[pj * 2 + 1][0] = r2; bh[pj * 2 + 1][1] = r3;
        }
        if (three) {
            unsigned bt[4][2];
#pragma unroll
            for (int pj = 0; pj < 2; pj++) {
                unsigned r0, r1, r2, r3;
                ldsm_x4(r0, r1, r2, r3,
                        bBase[pj] + boff + (unsigned)((((ks * 2 + kcB + 4)) ^ bSw[pj]) * 16));
                bt[pj * 2][0] = r0; bt[pj * 2][1] = r1;
                bt[pj * 2 + 1][0] = r2; bt[pj * 2 + 1][1] = r3;
            }
#pragma unroll
            for (int mi = 0; mi < 4; mi++) {
                unsigned a[4];
                ldsm_x4(a[0], a[1], a[2], a[3],
                        aBase[mi] + boff + (unsigned)((((ks * 2 + kcA)) ^ aSw[mi]) * 16));
#pragma unroll
                for (int nj = 0; nj < 4; nj++) mma_hf(acc[mi][nj], a, bh[nj]);
#pragma unroll
                for (int nj = 0; nj < 4; nj++) mma_hf(acc[mi][nj], a, bt[nj]);
                ldsm_x4(a[0], a[1], a[2], a[3],
                        aBase[mi] + boff + (unsigned)((((ks * 2 + kcA + 4)) ^ aSw[mi]) * 16));
#pragma unroll
                for (int nj = 0; nj < 4; nj++) mma_hf(acc[mi][nj], a, bh[nj]);
            }
        } else {
#pragma unroll
            for (int mi = 0; mi < 4; mi++) {
                unsigned a[4];
                ldsm_x4(a[0], a[1], a[2], a[3],
                        aBase[mi] + boff + (unsigned)((((ks * 2 + kcA)) ^ aSw[mi]) * 16));
#pragma unroll
                for (int nj = 0; nj < 4; nj++) mma_hf(acc[mi][nj], a, bh[nj]);
                if (NP == 2) {
                    ldsm_x4(a[0], a[1], a[2], a[3],
                            aBase[mi] + boff + (unsigned)((((ks * 2 + kcA + 4)) ^ aSw[mi]) * 16));
#pragma unroll
                    for (int nj = 0; nj < 4; nj++) mma_hf(acc[mi][nj], a, bh[nj]);
                }
            }
        }
    };

    issue(0, 0);
    const int nk = K >> 5;
    for (int it = 0; it < nk; it++) {
        asm volatile("cp.async.wait_group 0;" ::: "memory");
        __syncthreads();
        if (it + 1 < nk) issue((it + 1) * 32, (it + 1) & 1);
        const unsigned boff = (unsigned)((it & 1) * BUF_BYTES);
        do_ks(0, boff);
        do_ks(1, boff);
    }

    // epilogue
    const int row0 = m0 + wm * 64 + (lane >> 2);
    const int col0 = n0 + wn * 32 + (lane & 3) * 2;
#pragma unroll
    for (int mi = 0; mi < 4; mi++) {
#pragma unroll
        for (int nj = 0; nj < 4; nj++) {
            int col = col0 + nj * 8;
            if (col < N) {
                float b0 = 0.f, b1 = 0.f;
                if (EPI >= 1) { b0 = bias[col]; b1 = bias[col + 1]; }
                float v0 = acc[mi][nj][0] + b0;
                float v1 = acc[mi][nj][1] + b1;
                float v2 = acc[mi][nj][2] + b0;
                float v3 = acc[mi][nj][3] + b1;
                if (EPI == 2) {
                    v0 = v0 / (1.f + expf(-v0));
                    v1 = v1 / (1.f + expf(-v1));
                    v2 = v2 / (1.f + expf(-v2));
                    v3 = v3 / (1.f + expf(-v3));
                }
                int r = row0 + mi * 16;
                if (OSPLIT >= 1) {
                    __half h0 = __float2half(v0), h1 = __float2half(v1);
                    __half h2 = __float2half(v2), h3 = __float2half(v3);
                    *(unsigned*)&Chi[(size_t)r * N + col]       = pack16(*(unsigned short*)&h0, *(unsigned short*)&h1);
                    *(unsigned*)&Chi[(size_t)(r + 8) * N + col] = pack16(*(unsigned short*)&h2, *(unsigned short*)&h3);
                    if (OSPLIT == 1) {
                        __half l0 = __float2half(v0 - __half2float(h0));
                        __half l1 = __float2half(v1 - __half2float(h1));
                        __half l2 = __float2half(v2 - __half2float(h2));
                        __half l3 = __float2half(v3 - __half2float(h3));
                        *(unsigned*)&Clo[(size_t)r * N + col]       = pack16(*(unsigned short*)&l0, *(unsigned short*)&l1);
                        *(unsigned*)&Clo[(size_t)(r + 8) * N + col] = pack16(*(unsigned short*)&l2, *(unsigned short*)&l3);
                    }
                } else {
                    float2 p0; p0.x = v0; p0.y = v1;
                    float2 p1; p1.x = v2; p1.y = v3;
                    *(float2*)&C[(size_t)r * N + col] = p0;
                    *(float2*)&C[(size_t)(r + 8) * N + col] = p1;
                }
            }
        }
    }
}

// ---------------- vectorized splits ----------------
__global__ void __launch_bounds__(256)
split_hf4_kernel(const float* __restrict__ src, __half* __restrict__ hi,
                 __half* __restrict__ lo, int total4)
{
    int i4 = blockIdx.x * blockDim.x + threadIdx.x;
    if (i4 >= total4) return;
    int base = i4 * 4;
    float4 v = *(const float4*)&src[base];
    float f[4] = {v.x, v.y, v.z, v.w};
    unsigned short h[4], l[4];
#pragma unroll
    for (int j = 0; j < 4; j++) {
        __half hb = __float2half(f[j]);
        __half lb = __float2half(f[j] - __half2float(hb));
        h[j] = *(unsigned short*)&hb;
        l[j] = *(unsigned short*)&lb;
    }
    uint2 ho; ho.x = pack16(h[0], h[1]); ho.y = pack16(h[2], h[3]);
    uint2 lv; lv.x = pack16(l[0], l[1]); lv.y = pack16(l[2], l[3]);
    *(uint2*)&hi[base] = ho;
    *(uint2*)&lo[base] = lv;
}
__global__ void __launch_bounds__(256)
split_hf4p_kernel(const float* __restrict__ src, __half* __restrict__ hi,
                  __half* __restrict__ lo, int n, int total4)
{
    int i4 = blockIdx.x * blockDim.x + threadIdx.x;
    if (i4 >= total4) return;
    int base = i4 * 4;
    float f[4];
#pragma unroll
    for (int j = 0; j < 4; j++) f[j] = (base + j < n) ? src[base + j] : 0.f;
    unsigned short h[4], l[4];
#pragma unroll
    for (int j = 0; j < 4; j++) {
        __half hb = __float2half(f[j]);
        __half lb = __float2half(f[j] - __half2float(hb));
        h[j] = *(unsigned short*)&hb;
        l[j] = *(unsigned short*)&lb;
    }
    uint2 ho; ho.x = pack16(h[0], h[1]); ho.y = pack16(h[2], h[3]);
    uint2 lv; lv.x = pack16(l[0], l[1]); lv.y = pack16(l[2], l[3]);
    *(uint2*)&hi[base] = ho;
    *(uint2*)&lo[base] = lv;
}
__global__ void __launch_bounds__(256)
w1eff_split_kernel(const float* __restrict__ w1, __half* __restrict__ hi,
                   __half* __restrict__ lo)
{
    int i4 = blockIdx.x * blockDim.x + threadIdx.x;
    if (i4 >= 1024 * 512 / 4) return;
    int base = i4 * 4;
    int n = base / 512, k = base % 512;
    float4 a = *(const float4*)&w1[n * 1024 + k];
    float4 b = *(const float4*)&w1[n * 1024 + 512 + k];
    float f[4] = {a.x + b.x, a.y + b.y, a.z + b.z, a.w + b.w};
    unsigned short h[4], l[4];
#pragma unroll
    for (int j = 0; j < 4; j++) {
        __half hb = __float2half(f[j]);
        __half lb = __float2half(f[j] - __half2float(hb));
        h[j] = *(unsigned short*)&hb;
        l[j] = *(unsigned short*)&lb;
    }
    uint2 ho; ho.x = pack16(h[0], h[1]); ho.y = pack16(h[2], h[3]);
    uint2 lv; lv.x = pack16(l[0], l[1]); lv.y = pack16(l[2], l[3]);
    *(uint2*)&hi[base] = ho;
    *(uint2*)&lo[base] = lv;
}

// ---------------- conv (anti-causal) + silu, register-blocked (8 l per thread) ----
// block: 256 threads = 8 warps; warp w handles l-range [l0+w*8, l0+w*8+8) for
// 32 consecutive channels (lane = channel offset). Grid: CONVD/32 * LL/64 * BB.
__global__ void __launch_bounds__(256)
conv_silu_kernel(const float* __restrict__ zx, const float* __restrict__ cw,
                 const float* __restrict__ cb, float* __restrict__ xc)
{
    int blk = blockIdx.x;
    int ct  = blk % (CONVD / 32);
    int lt  = (blk / (CONVD / 32)) % (LL / 64);
    int b   = blk / ((CONVD / 32) * (LL / 64));
    int w   = threadIdx.x >> 5;
    int lane = threadIdx.x & 31;

    int c  = ct * 32 + lane;
    int l0 = lt * 64 + w * 8;

    float w0 = cw[c * 4 + 0];
    float w1 = cw[c * 4 + 1];
    float w2 = cw[c * 4 + 2];
    float w3 = cw[c * 4 + 3];
    float bias = cb[c];

    float vin[11];
    const float* base = zx + ((size_t)(b * LL)) * NPROJ + DINNER + c;
#pragma unroll
    for (int j = 0; j < 11; j++) {
        int lj = l0 + j;
        vin[j] = (lj < LL) ? base[(size_t)lj * NPROJ] : 0.f;
    }
    float* outb = xc + ((size_t)(b * LL)) * CONVD + c;
#pragma unroll
    for (int i = 0; i < 8; i++) {
        float acc = bias;
        acc += w0 * vin[i + 3];
        acc += w1 * vin[i + 2];
        acc += w2 * vin[i + 1];
        acc += w3 * vin[i];
        acc = acc / (1.f + expf(-acc));
        outb[(size_t)(l0 + i) * CONVD] = acc;
    }
}

// ---------------- scan pass 1 (occupancy-capped: 4 CTAs/SM) ----------------
__global__ void __launch_bounds__(256, 4)
scan_seg1_kernel(const float* __restrict__ zx, const float* __restrict__ xc,
                 const float* __restrict__ dt_bias, const float* __restrict__ A_log,
                 float* __restrict__ yout)
{
    int blk = blockIdx.x;
    int seg = blk & (SSEG - 1);
    int bh  = blk / SSEG;
    int b = bh >> 4, h = bh & 15;
    int tid = threadIdx.x;
    int pl = tid >> 2;
    int ng = tid & 3;

    float Acoef = -expf(A_log[h]);
    float dtb   = dt_bias[h];

    __shared__ float sB[2][8][64], sC[2][8][64], sX[2][8][64];
    __shared__ float sdt[2][8], sDA[2][8];

    float hs[16];
#pragma unroll
    for (int j = 0; j < 16; j++) hs[j] = 0.f;

    float rBC[4], rX[2], rDR = 0.f;
    const int sBeg = seg * SEGL;
    const int sEnd = sBeg + SEGL;

    float runP = 1.f;

    auto preload = [&](int s0) {
#pragma unroll
        for (int i = 0; i < 4; i++) {
            int e = tid + i * 256;
            int t = e >> 7, q = e & 127;
            int bl = b * LL + (LL - 1 - (s0 + t));
            rBC[i] = xc[(size_t)bl * CONVD + DINNER + q];
        }
#pragma unroll
        for (int i = 0; i < 2; i++) {
            int e = tid + i * 256;
            int t = e >> 6, j = e & 63;
            int bl = b * LL + (LL - 1 - (s0 + t));
            rX[i] = xc[(size_t)bl * CONVD + h * HEADD + j];
        }
        if (tid < 8) {
            int bl = b * LL + (LL - 1 - (s0 + tid));
            rDR = zx[(size_t)bl * NPROJ + (2 * DINNER + 2 * DSTATE) + h];
        }
    };
    auto commit_smem = [&](int buf) {
#pragma unroll
        for (int i = 0; i < 4; i++) {
            int e = tid + i * 256;
            int t = e >> 7, q = e & 127;
            if (q < 64) sB[buf][t][q] = rBC[i]; else sC[buf][t][q - 64] = rBC[i];
        }
#pragma unroll
        for (int i = 0; i < 2; i++) {
            int e = tid + i * 256;
            int t = e >> 6, j = e & 63;
            sX[buf][t][j] = rX[i];
        }
        if (tid < 8) {
            float dr = rDR + dtb;
            float dt = (dr > 20.f) ? dr : log1pf(expf(dr));
            sdt[buf][tid] = dt;
            sDA[buf][tid] = expf(dt * Acoef);
        }
    };

    preload(sBeg);
    commit_smem(0);
    __syncthreads();

    for (int s0 = sBeg; s0 < sEnd; s0 += 8) {
        int buf = ((s0 - sBeg) >> 3) & 1;
        bool more = (s0 + 8) < sEnd;
        if (more) preload(s0 + 8);

        if (tid == 0) {
            float* cw = &g_cum[(size_t)bh * LL + s0];
#pragma unroll
            for (int t = 0; t < 8; t++) { runP *= sDA[buf][t]; cw[t] = runP; }
        }

        float yv[8];
#pragma unroll
        for (int t = 0; t < 8; t++) {
            float dA  = sDA[buf][t];
            float dtx = sdt[buf][t] * sX[buf][t][pl];
            float yp = 0.f;
#pragma unroll
            for (int u = 0; u < 4; u++) {
                float4 bb = *(const float4*)&sB[buf][t][u * 16 + ng * 4];
                hs[u*4+0] = hs[u*4+0] * dA + dtx * bb.x;
                hs[u*4+1] = hs[u*4+1] * dA + dtx * bb.y;
                hs[u*4+2] = hs[u*4+2] * dA + dtx * bb.z;
                hs[u*4+3] = hs[u*4+3] * dA + dtx * bb.w;
            }
#pragma unroll
            for (int u = 0; u < 4; u++) {
                float4 cc = *(const float4*)&sC[buf][t][u * 16 + ng * 4];
                yp += hs[u*4+0] * cc.x + hs[u*4+1] * cc.y
                    + hs[u*4+2] * cc.z + hs[u*4+3] * cc.w;
            }
            yv[t] = yp;
        }
#pragma unroll
        for (int t = 0; t < 8; t++) yv[t] += __shfl_xor_sync(0xffffffffu, yv[t], 1);
#pragma unroll
        for (int t = 0; t < 8; t++) yv[t] += __shfl_xor_sync(0xffffffffu, yv[t], 2);
        if (ng == 0) {
#pragma unroll
            for (int t = 0; t < 8; t++) {
                int l = LL - 1 - (s0 + t);
                yout[((size_t)(b * LL + l)) * DINNER + h * HEADD + pl] = yv[t];
            }
        }

        if (more) commit_smem(buf ^ 1);
        __syncthreads();
    }

    {
        float* hd = &g_hseg[((size_t)blk) * 4096 + pl * 64];
#pragma unroll
        for (int j = 0; j < 16; j++) {
            int n = ((j >> 2) << 4) + (ng << 2) + (j & 3);
            hd[n] = hs[j];
        }
    }
}

// ---------------- scan pass 2 (parallelized: 512 blocks, float2/thread) --------
__global__ void __launch_bounds__(256)
scan_comb_kernel()
{
    int bh = blockIdx.x >> 3;
    int ch = blockIdx.x & 7;
    int e0 = ch * 512 + threadIdx.x * 2;
    float h0 = 0.f, h1 = 0.f;

    for (int seg = 0; seg < SSEG; seg++) {
        float P = g_cum[(size_t)bh * LL + seg * SEGL + SEGL - 1];
        size_t base = ((size_t)(bh * SSEG + seg)) * 4096 + e0;
        float2 hv = *(const float2*)&g_hseg[base];
        float2 st; st.x = h0; st.y = h1;
        *(float2*)&g_hst[base] = st;
        h0 = P * h0 + hv.x;
        h1 = P * h1 + hv.y;
    }
}

// ---------------- scan pass 3 (compacted grid: 64*(SSEG-1) blocks) ----------------
__global__ void __launch_bounds__(256, 4)
scan_fix_kernel(const float* __restrict__ xc, float* __restrict__ yout)
{
    int seg = 1 + (blockIdx.x % (SSEG - 1));
    int bh  = blockIdx.x / (SSEG - 1);
    int blk = bh * SSEG + seg;
    int b = bh >> 4, h = bh & 15;
    int tid = threadIdx.x;
    int pl = tid >> 2;
    int ng = tid & 3;

    float hs[16];
    {
        const float* hp = &g_hst[((size_t)blk) * 4096 + pl * 64];
#pragma unroll
        for (int j = 0; j < 16; j++) {
            int n = ((j >> 2) << 4) + (ng << 2) + (j & 3);
            hs[j] = hp[n];
        }
    }

    __shared__ float sC[8][64];
    __shared__ float sCum[8];
    const int sBeg = seg * SEGL;

    for (int s0 = sBeg; s0 < sBeg + SEGL; s0 += 8) {
#pragma unroll
        for (int i = 0; i < 2; i++) {
            int e = tid + i * 256;
            int t = e >> 6, q = e & 63;
            int bl = b * LL + (LL - 1 - (s0 + t));
            sC[t][q] = xc[(size_t)bl * CONVD + DINNER + DSTATE + q];
        }
        if (tid < 8) sCum[tid] = g_cum[(size_t)bh * LL + s0 + tid];
        __syncthreads();

        float yv[8];
#pragma unroll
        for (int t = 0; t < 8; t++) {
            float yp0 = 0.f, yp1 = 0.f, yp2 = 0.f, yp3 = 0.f;
#pragma unroll
            for (int u = 0; u < 4; u++) {
                float4 cc = *(const float4*)&sC[t][u * 16 + ng * 4];
                yp0 += hs[u*4+0] * cc.x;
                yp1 += hs[u*4+1] * cc.y;
                yp2 += hs[u*4+2] * cc.z;
                yp3 += hs[u*4+3] * cc.w;
            }
            yv[t] = ((yp0 + yp1) + (yp2 + yp3)) * sCum[t];
        }
#pragma unroll
        for (int t = 0; t < 8; t++) yv[t] += __shfl_xor_sync(0xffffffffu, yv[t], 1);
#pragma unroll
        for (int t = 0; t < 8; t++) yv[t] += __shfl_xor_sync(0xffffffffu, yv[t], 2);
        if (ng == 0) {
#pragma unroll
            for (int t = 0; t < 8; t++) {
                int l = LL - 1 - (s0 + t);
                size_t idx = ((size_t)(b * LL + l)) * DINNER + h * HEADD + pl;
                yout[idx] += yv[t];
            }
        }
        __syncthreads();
    }
}

// ---------------- block reduction helper ----------------
__device__ __forceinline__ float block_reduce_sum(float v) {
    __shared__ float sred[32];
    int lane = threadIdx.x & 31, w = threadIdx.x >> 5;
#pragma unroll
    for (int o = 16; o; o >>= 1) v += __shfl_xor_sync(0xffffffffu, v, o);
    if (lane == 0) sred[w] = v;
    __syncthreads();
    int nw = blockDim.x >> 5;
    float r = (threadIdx.x < nw) ? sred[threadIdx.x] : 0.f;
    if (w == 0) {
#pragma unroll
        for (int o = 16; o; o >>= 1) r += __shfl_xor_sync(0xffffffffu, r, o);
        if (lane == 0) sred[0] = r;
    }
    __syncthreads();
    float out = sred[0];
    __syncthreads();
    return out;
}

// ---------------- gate + rmsnorm -> split fp16 (vectorized) ----------------
__global__ void __launch_bounds__(256)
gate_rms_kernel(const float* __restrict__ ys, const float* __restrict__ xc,
                const float* __restrict__ zx, const float* __restrict__ Dv,
                const float* __restrict__ rw,
                __half* __restrict__ ybh, __half* __restrict__ ybl)
{
    int row = blockIdx.x;
    int c = threadIdx.x * 4;
    size_t oy = (size_t)row * DINNER, oc = (size_t)row * CONVD, oz = (size_t)row * NPROJ;
    float4 yv = *(const float4*)&ys[oy + c];
    float4 xv = *(const float4*)&xc[oc + c];
    float4 zv = *(const float4*)&zx[oz + c];
    float Dh = Dv[c >> 6];
    float v[4];
    {
        float z[4] = {zv.x, zv.y, zv.z, zv.w};
        float yy[4] = {yv.x, yv.y, yv.z, yv.w};
        float xx[4] = {xv.x, xv.y, xv.z, xv.w};
#pragma unroll
        for (int j = 0; j < 4; j++) {
            float sz = z[j] / (1.f + expf(-z[j]));
            v[j] = (yy[j] + Dh * xx[j]) * sz;
        }
    }
    float ss = v[0]*v[0] + v[1]*v[1] + v[2]*v[2] + v[3]*v[3];
    ss = block_reduce_sum(ss);
    float r = rsqrtf(ss * (1.f / (float)DINNER) + 1e-5f);
    float4 rwv = *(const float4*)&rw[c];
    float rr[4] = {rwv.x, rwv.y, rwv.z, rwv.w};
    unsigned short h[4], l[4];
#pragma unroll
    for (int j = 0; j < 4; j++) {
        float val = v[j] * r * rr[j];
        __half hh = __float2half(val);
        __half ll = __float2half(val - __half2float(hh));
        h[j] = *(unsigned short*)&hh;
        l[j] = *(unsigned short*)&ll;
    }
    uint2 ho; ho.x = pack16(h[0], h[1]); ho.y = pack16(h[2], h[3]);
    uint2 lo; lo.x = pack16(l[0], l[1]); lo.y = pack16(l[2], l[3]);
    *(uint2*)&ybh[oy + c] = ho;
    *(uint2*)&ybl[oy + c] = lo;
}

// ---------------- layernorm -> split fp16 (vectorized) ----------------
__global__ void __launch_bounds__(128)
layernorm_kernel(const float* __restrict__ x, const float* __restrict__ g,
                 const float* __restrict__ bpar,
                 __half* __restrict__ oh, __half* __restrict__ ol)
{
    int row = blockIdx.x;
    int c = threadIdx.x * 4;
    size_t o = (size_t)row * DMODEL;
    float4 xv = *(const float4*)&x[o + c];
    float v[4] = {xv.x, xv.y, xv.z, xv.w};
    float s = v[0] + v[1] + v[2] + v[3];
    s = block_reduce_sum(s);
    float m = s * (1.f / (float)DMODEL);
    float ss = 0.f;
#pragma unroll
    for (int j = 0; j < 4; j++) { float d = v[j] - m; ss += d * d; }
    ss = block_reduce_sum(ss);
    float r = rsqrtf(ss * (1.f / (float)DMODEL) + 1e-5f);
    float4 gv = *(const float4*)&g[c];
    float4 bv = *(const float4*)&bpar[c];
    float gg[4] = {gv.x, gv.y, gv.z, gv.w};
    float bb[4] = {bv.x, bv.y, bv.z, bv.w};
    unsigned short h[4], l[4];
#pragma unroll
    for (int j = 0; j < 4; j++) {
        float val = (v[j] - m) * r * gg[j] + bb[j];
        __half hh = __float2half(val);
        __half ll = __float2half(val - __half2float(hh));
        h[j] = *(unsigned short*)&hh;
        l[j] = *(unsigned short*)&ll;
    }
    uint2 ho; ho.x = pack16(h[0], h[1]); ho.y = pack16(h[2], h[3]);
    uint2 lo; lo.x = pack16(l[0], l[1]); lo.y = pack16(l[2], l[3]);
    *(uint2*)&oh[o + c] = ho;
    *(uint2*)&ol[o + c] = lo;
}

// ---------------- launch ----------------
extern "C" void kernel_launch(void* const* d_in, const int* in_sizes, int n_in,
                              void* d_out, int out_size)
{
    const float* x         = (const float*)d_in[0];
    const float* in_proj_w = (const float*)d_in[1];
    const float* conv_w    = (const float*)d_in[2];
    const float* conv_b    = (const float*)d_in[3];
    const float* dt_bias   = (const float*)d_in[4];
    const float* A_log     = (const float*)d_in[5];
    const float* Dv        = (const float*)d_in[6];
    const float* rms_w     = (const float*)d_in[7];
    const float* out_proj  = (const float*)d_in[8];
    const float* ln_g      = (const float*)d_in[9];
    const float* ln_b      = (const float*)d_in[10];
    const float* w1        = (const float*)d_in[11];
    const float* b1        = (const float*)d_in[12];
    const float* w2        = (const float*)d_in[13];
    const float* b2        = (const float*)d_in[14];
    float* outp            = (float*)d_out;

    float *p_zx, *p_xc, *p_ys, *p_y2;
    cudaGetSymbolAddress((void**)&p_zx,  g_zx);
    cudaGetSymbolAddress((void**)&p_xc,  g_xc);
    cudaGetSymbolAddress((void**)&p_ys,  g_ys);
    cudaGetSymbolAddress((void**)&p_y2,  g_y2);

    __half *p_xhi, *p_xlo, *p_winh, *p_winl;
    __half *p_woh, *p_wol, *p_w1h, *p_w1l, *p_w2h, *p_w2l;
    __half *p_ybh, *p_ybl, *p_ylnh, *p_ylnl, *p_h1h, *p_h1l;
    cudaGetSymbolAddress((void**)&p_xhi,  g_xhi);
    cudaGetSymbolAddress((void**)&p_xlo,  g_xlo);
    cudaGetSymbolAddress((void**)&p_winh, g_winh);
    cudaGetSymbolAddress((void**)&p_winl, g_winl);
    cudaGetSymbolAddress((void**)&p_woh,  g_woh);
    cudaGetSymbolAddress((void**)&p_wol,  g_wol);
    cudaGetSymbolAddress((void**)&p_w1h,  g_w1h);
    cudaGetSymbolAddress((void**)&p_w1l,  g_w1l);
    cudaGetSymbolAddress((void**)&p_w2h,  g_w2h);
    cudaGetSymbolAddress((void**)&p_w2l,  g_w2l);
    cudaGetSymbolAddress((void**)&p_ybh,  g_ybh);
    cudaGetSymbolAddress((void**)&p_ybl,  g_ybl);
    cudaGetSymbolAddress((void**)&p_ylnh, g_ylnh);
    cudaGetSymbolAddress((void**)&p_ylnl, g_ylnl);
    cudaGetSymbolAddress((void**)&p_h1h,  g_h1h);
    cudaGetSymbolAddress((void**)&p_h1l,  g_h1l);

    static bool attr_done = false;
    if (!attr_done) {
        cudaFuncSetAttribute(hgemm2_kernel<0,0,2>, cudaFuncAttributeMaxDynamicSharedMemorySize, GSM_BYTES);
        cudaFuncSetAttribute(hgemm2_kernel<2,2,1>, cudaFuncAttributeMaxDynamicSharedMemorySize, GSM_BYTES);
        cudaFuncSetAttribute(hgemm2_kernel<1,0,1>, cudaFuncAttributeMaxDynamicSharedMemorySize, GSM_BYTES);
        attr_done = true;
    }

    // operand splitting (vectorized, all fp16)
    {
        int n, tot4;
        tot4 = BL * DMODEL / 4;
        split_hf4_kernel<<<(tot4 + 255) / 256, 256>>>(x, p_xhi, p_xlo, tot4);
        n = NPROJ * DMODEL; tot4 = NPROJ_PAD * DMODEL / 4;
        split_hf4p_kernel<<<(tot4 + 255) / 256, 256>>>(in_proj_w, p_winh, p_winl, n, tot4);
        tot4 = DMODEL * DINNER / 4;
        split_hf4_kernel<<<(tot4 + 255) / 256, 256>>>(out_proj, p_woh, p_wol, tot4);
        split_hf4_kernel<<<(tot4 + 255) / 256, 256>>>(w2, p_w2h, p_w2l, tot4);
        w1eff_split_kernel<<<(1024 * 512 / 4 + 255) / 256, 256>>>(w1, p_w1h, p_w1l);
    }

    // 1) in_proj (fp16 2-pass; dt tile n0>=2176 3-pass)
    {
        dim3 grid(NPROJ_PAD / 128, BL / 128);
        hgemm2_kernel<0,0,2><<<grid, 256, GSM_BYTES>>>(p_xhi, p_xlo, p_winh, p_winl,
                                                       nullptr, p_zx, nullptr, nullptr,
                                                       BL, NPROJ, DMODEL, 2176);
    }
    // 2) conv + silu (register-blocked)
    {
        int blocks = BB * (LL / 64) * (CONVD / 32);
        conv_silu_kernel<<<blocks, 256>>>(p_zx, conv_w, conv_b, p_xc);
    }
    // 3) segmented selective scan
    scan_seg1_kernel<<<64 * SSEG, 256>>>(p_zx, p_xc, dt_bias, A_log, p_ys);
    scan_comb_kernel<<<64 * 8, 256>>>();
    scan_fix_kernel<<<64 * (SSEG - 1), 256>>>(p_xc, p_ys);
    // 4) gate + rmsnorm -> fp16 split
    gate_rms_kernel<<<BL, 256>>>(p_ys, p_xc, p_zx, Dv, rms_w, p_ybh, p_ybl);
    // 5) out_proj (fp16 2-pass)
    {
        dim3 grid(DMODEL / 128, BL / 128);
        hgemm2_kernel<0,0,2><<<grid, 256, GSM_BYTES>>>(p_ybh, p_ybl, p_woh, nullptr,
                                                       nullptr, p_y2, nullptr, nullptr,
                                                       BL, DMODEL, DINNER, DMODEL);
    }
    // 6) layernorm -> fp16 split
    layernorm_kernel<<<BL, 128>>>(p_y2, ln_g, ln_b, p_ylnh, p_ylnl);
    // 7) mlp hidden (fp16 1-pass, bias + silu, hi-only out)
    {
        dim3 grid(DINNER / 128, BL / 128);
        hgemm2_kernel<2,2,1><<<grid, 256, GSM_BYTES>>>(p_ylnh, p_ylnl, p_w1h, nullptr,
                                                       b1, nullptr, p_h1h, p_h1l,
                                                       BL, DINNER, DMODEL, DINNER);
    }
    // 8) output (fp16 1-pass, bias)
    {
        dim3 grid(DMODEL / 128, BL / 128);
        hgemm2_kernel<1,0,1><<<grid, 256, GSM_BYTES>>>(p_h1h, p_h1l, p_w2h, nullptr,
                                                       b2, outp, nullptr, nullptr,
                                                       BL, DMODEL, DINNER, DMODEL);
    }
}